// round 12
// baseline (speedup 1.0000x reference)
#include <cuda_runtime.h>
#include <cuda_fp16.h>
#include <math.h>
#include <stdint.h>

// ---------------- problem constants ----------------
#define BATCH   2
#define HT      64
#define WT      64
#define CDIM    768
#define WIN     14
#define NWIN1   5
#define NWINB   25
#define NW      50
#define HW      196
#define NHEAD   12
#define HD      64
#define MLPD    3072
#define TOKG    (BATCH*HT*WT)  // 8192 global tokens
#define EPS     1e-5f

// ---------------- scratch (global token layout everywhere) ----------------
__device__ __half g_xn1 [TOKG * CDIM];       // LN1 out (half)
__device__ __half g_qkv [TOKG * 3 * CDIM];   // qkv (half)
__device__ __half g_attn[TOKG * CDIM];       // attention out (half)
__device__ float  g_x2  [TOKG * CDIM];       // x + attn (float)
__device__ __half g_xn2 [TOKG * CDIM];       // LN2 out (half)
__device__ __half g_hid [TOKG * MLPD];       // MLP hidden (half)
__device__ __half g_wqkvT[3 * CDIM * CDIM];  // transposed half weights [n][k]
__device__ __half g_wprojT[CDIM * CDIM];
__device__ __half g_w1T  [MLPD * CDIM];
__device__ __half g_w2T  [CDIM * MLPD];

// ---------------- helpers ----------------
__device__ __forceinline__ void win_map(int row, int& gidx, bool& valid) {
    int n  = row / HW, t = row % HW;
    int bb = n / NWINB, nw = n % NWINB;
    int wh = nw / NWIN1, ww = nw % NWIN1;
    int ii = t / WIN,    jj = t % WIN;
    int gh = wh * WIN + ii, gw = ww * WIN + jj;
    valid = (gh < HT) && (gw < WT);
    gidx  = (bb * HT + gh) * WT + gw;
}
__device__ __forceinline__ uint32_t smem_u32(const void* p) {
    return (uint32_t)__cvta_generic_to_shared(p);
}
__device__ __forceinline__ void cp16(uint32_t dst, const void* src) {
    asm volatile("cp.async.cg.shared.global [%0], [%1], 16;\n"
                 :: "r"(dst), "l"(src));
}
__device__ __forceinline__ void ldsm4(uint32_t& r0, uint32_t& r1,
                                      uint32_t& r2, uint32_t& r3, uint32_t a) {
    asm volatile("ldmatrix.sync.aligned.m8n8.x4.shared.b16 {%0,%1,%2,%3}, [%4];"
                 : "=r"(r0), "=r"(r1), "=r"(r2), "=r"(r3) : "r"(a));
}
__device__ __forceinline__ void mma16816(float* c, const uint32_t* a,
                                         const uint32_t* b) {
    asm volatile(
        "mma.sync.aligned.m16n8k16.row.col.f32.f16.f16.f32 "
        "{%0,%1,%2,%3}, {%4,%5,%6,%7}, {%8,%9}, {%0,%1,%2,%3};\n"
        : "+f"(c[0]), "+f"(c[1]), "+f"(c[2]), "+f"(c[3])
        : "r"(a[0]), "r"(a[1]), "r"(a[2]), "r"(a[3]),
          "r"(b[0]), "r"(b[1]));
}

// ---------------- weight transpose + fp32->fp16 ----------------
__global__ __launch_bounds__(256) void f2hT_kernel(
    const float* __restrict__ src, __half* __restrict__ dst, int K, int N)
{
    __shared__ float t[32][33];
    int n0 = blockIdx.x * 32, k0 = blockIdx.y * 32;
    int tx = threadIdx.x, ty = threadIdx.y;
    #pragma unroll
    for (int i = 0; i < 32; i += 8)
        t[ty + i][tx] = src[(size_t)(k0 + ty + i) * N + n0 + tx];
    __syncthreads();
    #pragma unroll
    for (int i = 0; i < 32; i += 8)
        dst[(size_t)(n0 + ty + i) * K + k0 + tx] = __float2half_rn(t[tx][ty + i]);
}

// ---------------- LayerNorm (float in -> half out), 8192 rows ---------------
__global__ __launch_bounds__(256) void ln_kernel(
    const float* __restrict__ in, __half* __restrict__ outp,
    const float* __restrict__ g, const float* __restrict__ b)
{
    int row = blockIdx.x;
    int tid = threadIdx.x;
    const float* xr = in + (size_t)row * CDIM;
    __half* orow = outp + (size_t)row * CDIM;
    float v[3]; float s = 0.f, sq = 0.f;
    #pragma unroll
    for (int u = 0; u < 3; u++) {
        v[u] = xr[tid + u * 256];
        s += v[u]; sq += v[u] * v[u];
    }
    __shared__ float red[2][8];
    #pragma unroll
    for (int off = 16; off; off >>= 1) {
        s  += __shfl_xor_sync(~0u, s,  off);
        sq += __shfl_xor_sync(~0u, sq, off);
    }
    if ((tid & 31) == 0) { red[0][tid >> 5] = s; red[1][tid >> 5] = sq; }
    __syncthreads();
    if (tid < 32) {
        float a = (tid < 8) ? red[0][tid] : 0.f;
        float c = (tid < 8) ? red[1][tid] : 0.f;
        #pragma unroll
        for (int off = 4; off; off >>= 1) {
            a += __shfl_xor_sync(~0u, a, off);
            c += __shfl_xor_sync(~0u, c, off);
        }
        if (tid == 0) { red[0][0] = a; red[1][0] = c; }
    }
    __syncthreads();
    float mean = red[0][0] * (1.f / CDIM);
    float var  = red[1][0] * (1.f / CDIM) - mean * mean;
    float rstd = rsqrtf(var + EPS);
    #pragma unroll
    for (int u = 0; u < 3; u++) {
        int c = tid + u * 256;
        orow[c] = __float2half_rn((v[u] - mean) * rstd * g[c] + b[c]);
    }
}

// ---------------- FP16 GEMM: 128x256 tile, warp 64x64, 3-stage cp.async -----
// C[M,N] = A[M,K](half) @ Bt[N,K](half)^T + bias.  M%128==0, N%256==0.
// mode 0: half store   1: exact GELU -> half   2: acc+bias+res -> float
#define KTILE  32
#define AST    40                      // halfs per row (32 + 8 pad)
#define ASTG_H (128 * AST)             // A stage halfs
#define BSTG_H (256 * AST)             // B stage halfs
#define ASTG_B (ASTG_H * 2)            // 10240 B
#define BSTG_B (BSTG_H * 2)            // 20480 B
#define GSMEM  (3 * (ASTG_B + BSTG_B)) // 92160 B

__global__ __launch_bounds__(256, 1) void hgemm_kernel(
    const __half* __restrict__ A, const __half* __restrict__ Bt,
    const float* __restrict__ bias, const float* __restrict__ res,
    float* __restrict__ Cf, __half* __restrict__ Ch,
    int M, int N, int K, int mode)
{
    extern __shared__ __half shh[];
    __half* AsS = shh;                     // [3][128][AST]
    __half* BsS = shh + 3 * ASTG_H;        // [3][256][AST]

    int tid  = threadIdx.x;
    int warp = tid >> 5, lane = tid & 31;
    int wm = warp >> 2, wn = warp & 3;     // 2x4 warps, warp tile 64x64
    int gq = lane >> 2, tr = lane & 3;
    int bm = blockIdx.y * 128, bn = blockIdx.x * 256;

    // A staging: row tid>>1, 16 halfs at (tid&1)*16  (2 cp16/thread)
    int arow = tid >> 1;
    int acol = (tid & 1) * 16;
    const __half* Ag = A + (size_t)(bm + arow) * K + acol;
    uint32_t as_st = smem_u32(AsS + arow * AST + acol);
    // B staging: row tid, 32 halfs (4 cp16/thread)
    const __half* Bg = Bt + (size_t)(bn + tid) * K;
    uint32_t bs_st = smem_u32(BsS + tid * AST);

    uint32_t as_base = smem_u32(AsS);
    uint32_t bs_base = smem_u32(BsS);
    int fr = lane & 15;
    int fc = (lane >> 4) * 8;

    float acc[4][8][4];
    #pragma unroll
    for (int mi = 0; mi < 4; mi++)
        #pragma unroll
        for (int ni = 0; ni < 8; ni++)
            #pragma unroll
            for (int r = 0; r < 4; r++) acc[mi][ni][r] = 0.f;

    int T = K / KTILE;

    #define FILL(t, s) do {                                        \
        const __half* ag_ = Ag + (t) * KTILE;                      \
        uint32_t ad_ = as_st + (s) * ASTG_B;                       \
        cp16(ad_,      ag_);                                       \
        cp16(ad_ + 16, ag_ + 8);                                   \
        const __half* bg_ = Bg + (t) * KTILE;                      \
        uint32_t bd_ = bs_st + (s) * BSTG_B;                       \
        cp16(bd_,      bg_);      cp16(bd_ + 16, bg_ + 8);         \
        cp16(bd_ + 32, bg_ + 16); cp16(bd_ + 48, bg_ + 24);        \
        asm volatile("cp.async.commit_group;\n");                  \
    } while (0)

    FILL(0, 0);
    FILL(1, 1);

    int s = 0;
    for (int t = 0; t < T; t++) {
        if (t + 1 < T) asm volatile("cp.async.wait_group 1;\n");
        else           asm volatile("cp.async.wait_group 0;\n");
        __syncthreads();
        if (t + 2 < T) {
            int sf = (s == 0) ? 2 : s - 1;
            FILL(t + 2, sf);
        }

        uint32_t ab = as_base + s * ASTG_B;
        uint32_t bb = bs_base + s * BSTG_B;
        #pragma unroll
        for (int kk = 0; kk < KTILE; kk += 16) {
            uint32_t af[4][4], bf[8][2];
            #pragma unroll
            for (int mi = 0; mi < 4; mi++) {
                uint32_t addr = ab +
                    (((wm * 64 + mi * 16 + fr) * AST) + kk + fc) * 2;
                ldsm4(af[mi][0], af[mi][1], af[mi][2], af[mi][3], addr);
            }
            #pragma unroll
            for (int nh = 0; nh < 4; nh++) {
                uint32_t addr = bb +
                    (((wn * 64 + nh * 16 + fr) * AST) + kk + fc) * 2;
                ldsm4(bf[2 * nh][0], bf[2 * nh + 1][0],
                      bf[2 * nh][1], bf[2 * nh + 1][1], addr);
            }
            #pragma unroll
            for (int mi = 0; mi < 4; mi++)
                #pragma unroll
                for (int ni = 0; ni < 8; ni++)
                    mma16816(acc[mi][ni], af[mi], bf[ni]);
        }
        s = (s == 2) ? 0 : s + 1;
    }
    #undef FILL

    // ---------------- epilogue ----------------
    #pragma unroll
    for (int mi = 0; mi < 4; mi++) {
        int rbase = bm + wm * 64 + mi * 16 + gq;
        #pragma unroll
        for (int h = 0; h < 2; h++) {
            int row = rbase + 8 * h;
            #pragma unroll
            for (int ni = 0; ni < 8; ni++) {
                int col = bn + wn * 64 + ni * 8 + tr * 2;
                float v0 = acc[mi][ni][2 * h]     + bias[col];
                float v1 = acc[mi][ni][2 * h + 1] + bias[col + 1];
                if (mode == 0) {
                    *(__half2*)&Ch[(size_t)row * N + col] =
                        __floats2half2_rn(v0, v1);
                } else if (mode == 1) {
                    v0 = 0.5f * v0 * (1.f + erff(v0 * 0.70710678118654752f));
                    v1 = 0.5f * v1 * (1.f + erff(v1 * 0.70710678118654752f));
                    *(__half2*)&Ch[(size_t)row * N + col] =
                        __floats2half2_rn(v0, v1);
                } else {
                    Cf[(size_t)row * N + col]     = v0 + res[(size_t)row * N + col];
                    Cf[(size_t)row * N + col + 1] = v1 + res[(size_t)row * N + col + 1];
                }
            }
        }
    }
}

// ---------------- tensor-core window attention (gathers via gtab) -----------
#define QKS   72
#define VPS   216
#define SSX   212
#define F_S   0
#define F_BH  (64 * SSX)
#define F_BW  (F_BH + HW * WIN)
#define F_RH  (F_BW + HW * WIN)
#define F_RW  (F_RH + 27 * HD)
#define F_GT  (F_RW + 27 * HD)
#define F_TOT (F_GT + HW)
#define H_Q   0
#define H_K   (HW * QKS)
#define H_VT  (H_K + HW * QKS)
#define H_P   (H_VT + HD * VPS)
#define H_TOT (H_P + 64 * VPS)
#define ATTN_SMEM_BYTES (F_TOT * 4 + H_TOT * 2)

__global__ __launch_bounds__(256, 1) void attn_kernel(
    const float* __restrict__ rel_h, const float* __restrict__ rel_w,
    const float* __restrict__ b_qkv)
{
    extern __shared__ float smf[];
    float* Ss = smf + F_S;
    float* bh = smf + F_BH;
    float* bw = smf + F_BW;
    float* rhs = smf + F_RH;
    float* rws = smf + F_RW;
    int*   gtab = (int*)(smf + F_GT);
    __half* hbase = (__half*)(smf + F_TOT);
    __half* qs  = hbase + H_Q;
    __half* kss = hbase + H_K;
    __half* vts = hbase + H_VT;
    __half* ps  = hbase + H_P;

    int w0   = blockIdx.x;
    int head = blockIdx.y;
    int tid  = threadIdx.x;
    int warp = tid >> 5, lane = tid & 31;
    int gq = lane >> 2, tr = lane & 3;
    int fr = lane & 15;
    int fc = (lane >> 4) * 8;

    uint32_t qs_b  = smem_u32(qs);
    uint32_t ks_b  = smem_u32(kss);
    uint32_t vt_b  = smem_u32(vts);
    uint32_t ps_b  = smem_u32(ps);

    if (tid < HW) {
        int gi; bool v;
        win_map(w0 * HW + tid, gi, v);
        gtab[tid] = v ? gi : -1;
    }
    for (int idx = tid; idx < 27 * HD; idx += 256) {
        rhs[idx] = rel_h[idx];
        rws[idx] = rel_w[idx];
    }
    __syncthreads();

    const float* bq = b_qkv + head * HD;
    for (int idx = tid; idx < HW * 16; idx += 256) {
        int row = idx >> 4, d = (idx & 15) * 4;
        int gi = gtab[row];
        if (gi >= 0) {
            const __half* src = g_qkv + (size_t)gi * (3 * CDIM) + head * HD + d;
            *(uint2*)&qs [row * QKS + d] = *(const uint2*)(src);
            *(uint2*)&kss[row * QKS + d] = *(const uint2*)(src + CDIM);
        } else {
            #pragma unroll
            for (int j = 0; j < 4; j++) {
                qs [row * QKS + d + j] = __float2half_rn(bq[d + j]);
                kss[row * QKS + d + j] = __float2half_rn(bq[CDIM + d + j]);
            }
        }
    }
    for (int idx = tid; idx < HW * HD; idx += 256) {
        int key = idx >> 6, d = idx & 63;
        int gi = gtab[key];
        vts[d * VPS + key] = (gi >= 0)
            ? g_qkv[(size_t)gi * (3 * CDIM) + 2 * CDIM + head * HD + d]
            : __float2half_rn(bq[2 * CDIM + d]);
    }
    for (int idx = tid; idx < HD * 12; idx += 256) {
        int d = idx / 12;
        vts[d * VPS + HW + idx % 12] = __float2half_rn(0.f);
    }
    __syncthreads();

    for (int j = tid; j < HW * 28; j += 256) {
        int q = j / 28, wch = j % 28;
        int hq = q / WIN, wq = q % WIN;
        const float* tab;
        int o;
        if (wch < 14) { tab = rhs; o = (hq - wch + (WIN - 1)) * HD; }
        else          { tab = rws; o = (wq - (wch - 14) + (WIN - 1)) * HD; }
        float acc = 0.f;
        #pragma unroll
        for (int d = 0; d < HD; d += 4) {
            uint2 hv = *(const uint2*)&qs[q * QKS + d];
            float2 f0 = __half22float2(*(__half2*)&hv.x);
            float2 f1 = __half22float2(*(__half2*)&hv.y);
            float4 t4 = *(const float4*)&tab[o + d];
            acc += f0.x * t4.x + f0.y * t4.y + f1.x * t4.z + f1.y * t4.w;
        }
        if (wch < 14) bh[q * WIN + wch] = acc;
        else          bw[q * WIN + wch - 14] = acc;
    }
    __syncthreads();

    int stripe = warp >> 1, nh = warp & 1;
    int ngr   = nh ? 6 : 7;
    int nbase = nh ? 112 : 0;

    for (int c = 0; c < 4; c++) {
        int q0 = c * 64;
        int rows = (HW - q0 < 64) ? (HW - q0) : 64;
        int nstripes = (rows + 15) >> 4;

        if (stripe < nstripes) {
            int mrow = q0 + stripe * 16;
            float sacc[7][2][4];
            #pragma unroll
            for (int g = 0; g < 7; g++)
                #pragma unroll
                for (int u = 0; u < 2; u++)
                    #pragma unroll
                    for (int r = 0; r < 4; r++) sacc[g][u][r] = 0.f;

            #pragma unroll
            for (int kk = 0; kk < HD; kk += 16) {
                uint32_t af[4];
                int ar = mrow + fr; if (ar > HW - 1) ar = HW - 1;
                ldsm4(af[0], af[1], af[2], af[3],
                      qs_b + (ar * QKS + kk + fc) * 2);
                for (int g = 0; g < ngr; g++) {
                    int br = nbase + g * 16 + fr; if (br > HW - 1) br = HW - 1;
                    uint32_t bf0[2], bf1[2];
                    ldsm4(bf0[0], bf1[0], bf0[1], bf1[1],
                          ks_b + (br * QKS + kk + fc) * 2);
                    mma16816(sacc[g][0], af, bf0);
                    mma16816(sacc[g][1], af, bf1);
                }
            }
            for (int g = 0; g < ngr; g++) {
                #pragma unroll
                for (int u = 0; u < 2; u++) {
                    int col = nbase + g * 16 + u * 8 + tr * 2;
                    int r0 = stripe * 16 + gq;
                    *(float2*)&Ss[r0 * SSX + col] =
                        make_float2(sacc[g][u][0], sacc[g][u][1]);
                    *(float2*)&Ss[(r0 + 8) * SSX + col] =
                        make_float2(sacc[g][u][2], sacc[g][u][3]);
                }
            }
        }
        __syncthreads();

        for (int r = warp; r < rows; r += 8) {
            int q = q0 + r;
            float v[7];
            float mx = -1e30f;
            #pragma unroll
            for (int i = 0; i < 7; i++) {
                int col = lane + 32 * i;
                if (col < HW) {
                    float sv = Ss[r * SSX + col] * 0.125f
                             + bh[q * WIN + col / WIN]
                             + bw[q * WIN + col % WIN];
                    v[i] = sv;
                    mx = fmaxf(mx, sv);
                } else v[i] = -1e30f;
            }
            #pragma unroll
            for (int off = 16; off; off >>= 1)
                mx = fmaxf(mx, __shfl_xor_sync(~0u, mx, off));
            float sum = 0.f;
            #pragma unroll
            for (int i = 0; i < 7; i++) {
                int col = lane + 32 * i;
                if (col < HW) { float e = __expf(v[i] - mx); v[i] = e; sum += e; }
                else v[i] = 0.f;
            }
            #pragma unroll
            for (int off = 16; off; off >>= 1)
                sum += __shfl_xor_sync(~0u, sum, off);
            float inv = 1.f / sum;
            #pragma unroll
            for (int i = 0; i < 7; i++) {
                int col = lane + 32 * i;
                if (col < HW)       ps[r * VPS + col] = __float2half_rn(v[i] * inv);
                else if (col < 208) ps[r * VPS + col] = __float2half_rn(0.f);
            }
        }
        __syncthreads();

        if (stripe < nstripes) {
            int d0b = nh * 32;
            float oacc[4][4];
            #pragma unroll
            for (int ni = 0; ni < 4; ni++)
                #pragma unroll
                for (int r = 0; r < 4; r++) oacc[ni][r] = 0.f;

            for (int kk = 0; kk < 208; kk += 16) {
                uint32_t af[4];
                ldsm4(af[0], af[1], af[2], af[3],
                      ps_b + ((stripe * 16 + fr) * VPS + kk + fc) * 2);
                #pragma unroll
                for (int g = 0; g < 2; g++) {
                    uint32_t bf0[2], bf1[2];
                    ldsm4(bf0[0], bf1[0], bf0[1], bf1[1],
                          vt_b + ((d0b + g * 16 + fr) * VPS + kk + fc) * 2);
                    mma16816(oacc[2 * g],     af, bf0);
                    mma16816(oacc[2 * g + 1], af, bf1);
                }
            }
            #pragma unroll
            for (int ni = 0; ni < 4; ni++) {
                int col = head * HD + d0b + ni * 8 + tr * 2;
                #pragma unroll
                for (int h = 0; h < 2; h++) {
                    int grow = q0 + stripe * 16 + gq + 8 * h;
                    if (grow < HW) {
                        int gi = gtab[grow];
                        if (gi >= 0) {
                            __half* op = g_attn + (size_t)gi * CDIM + col;
                            *(__half2*)op = __floats2half2_rn(oacc[ni][2 * h],
                                                              oacc[ni][2 * h + 1]);
                        }
                    }
                }
            }
        }
        __syncthreads();
    }
}

// ---------------- launcher ----------------
extern "C" void kernel_launch(void* const* d_in, const int* in_sizes, int n_in,
                              void* d_out, int out_size)
{
    const float* x      = (const float*)d_in[0];
    const float* g1     = (const float*)d_in[1];
    const float* b1     = (const float*)d_in[2];
    const float* w_qkv  = (const float*)d_in[3];
    const float* b_qkv  = (const float*)d_in[4];
    const float* w_proj = (const float*)d_in[5];
    const float* b_proj = (const float*)d_in[6];
    const float* rel_h  = (const float*)d_in[7];
    const float* rel_w  = (const float*)d_in[8];
    const float* g2     = (const float*)d_in[9];
    const float* b2     = (const float*)d_in[10];
    const float* w1     = (const float*)d_in[11];
    const float* b1m    = (const float*)d_in[12];
    const float* w2     = (const float*)d_in[13];
    const float* b2m    = (const float*)d_in[14];
    float* out = (float*)d_out;

    __half *p_xn1, *p_qkv, *p_attn, *p_xn2, *p_hid;
    __half *p_wqkvT, *p_wprojT, *p_w1T, *p_w2T;
    float *p_x2;
    cudaGetSymbolAddress((void**)&p_xn1,   g_xn1);
    cudaGetSymbolAddress((void**)&p_qkv,   g_qkv);
    cudaGetSymbolAddress((void**)&p_attn,  g_attn);
    cudaGetSymbolAddress((void**)&p_x2,    g_x2);
    cudaGetSymbolAddress((void**)&p_xn2,   g_xn2);
    cudaGetSymbolAddress((void**)&p_hid,   g_hid);
    cudaGetSymbolAddress((void**)&p_wqkvT, g_wqkvT);
    cudaGetSymbolAddress((void**)&p_wprojT,g_wprojT);
    cudaGetSymbolAddress((void**)&p_w1T,   g_w1T);
    cudaGetSymbolAddress((void**)&p_w2T,   g_w2T);

    static int attr_set = 0;
    if (!attr_set) {
        cudaFuncSetAttribute(attn_kernel,
            cudaFuncAttributeMaxDynamicSharedMemorySize, ATTN_SMEM_BYTES);
        cudaFuncSetAttribute(hgemm_kernel,
            cudaFuncAttributeMaxDynamicSharedMemorySize, GSMEM);
        attr_set = 1;
    }

    dim3 tb(32, 8);
    f2hT_kernel<<<dim3((3 * CDIM) / 32, CDIM / 32), tb>>>(w_qkv,  p_wqkvT, CDIM, 3 * CDIM);
    f2hT_kernel<<<dim3(CDIM / 32, CDIM / 32),       tb>>>(w_proj, p_wprojT, CDIM, CDIM);
    f2hT_kernel<<<dim3(MLPD / 32, CDIM / 32),       tb>>>(w1,     p_w1T, CDIM, MLPD);
    f2hT_kernel<<<dim3(CDIM / 32, MLPD / 32),       tb>>>(w2,     p_w2T, MLPD, CDIM);

    // 1) LN1 (global layout) -> g_xn1 (half)
    ln_kernel<<<TOKG, 256>>>(x, p_xn1, g1, b1);

    // 2) QKV GEMM: [8192,768] @ [768,2304] -> g_qkv (half)
    {
        dim3 grid((3 * CDIM) / 256, TOKG / 128);
        hgemm_kernel<<<grid, 256, GSMEM>>>(p_xn1, p_wqkvT, b_qkv, nullptr,
                                           nullptr, p_qkv,
                                           TOKG, 3 * CDIM, CDIM, 0);
    }

    // 3) tensor-core attention (window gather) -> g_attn (half, global layout)
    attn_kernel<<<dim3(NW, NHEAD), 256, ATTN_SMEM_BYTES>>>(rel_h, rel_w, b_qkv);

    // 4) proj GEMM + residual(x) -> g_x2 (float)
    {
        dim3 grid(CDIM / 256, TOKG / 128);
        hgemm_kernel<<<grid, 256, GSMEM>>>(p_attn, p_wprojT, b_proj, x,
                                           p_x2, nullptr,
                                           TOKG, CDIM, CDIM, 2);
    }

    // 5) LN2 -> g_xn2 (half)
    ln_kernel<<<TOKG, 256>>>(p_x2, p_xn2, g2, b2);

    // 6) FC1 + GELU -> g_hid (half)
    {
        dim3 grid(MLPD / 256, TOKG / 128);
        hgemm_kernel<<<grid, 256, GSMEM>>>(p_xn2, p_w1T, b1m, nullptr,
                                           nullptr, p_hid,
                                           TOKG, MLPD, CDIM, 1);
    }

    // 7) FC2 + residual(g_x2) -> out (float)
    {
        dim3 grid(CDIM / 256, TOKG / 128);
        hgemm_kernel<<<grid, 256, GSMEM>>>(p_hid, p_w2T, b2m, p_x2,
                                           out, nullptr,
                                           TOKG, CDIM, MLPD, 2);
    }
}

// round 14
// speedup vs baseline: 1.1756x; 1.1756x over previous
#include <cuda_runtime.h>
#include <cuda_fp16.h>
#include <math.h>
#include <stdint.h>

// ---------------- problem constants ----------------
#define BATCH   2
#define HT      64
#define WT      64
#define CDIM    768
#define WIN     14
#define NWIN1   5
#define NWINB   25
#define NW      50
#define HW      196
#define NHEAD   12
#define HD      64
#define MLPD    3072
#define TOKG    (BATCH*HT*WT)  // 8192 global tokens
#define EPS     1e-5f

// ---------------- scratch (global token layout everywhere) ----------------
__device__ __half g_xn1 [TOKG * CDIM];       // LN1 out (half)
__device__ __half g_qkv [TOKG * 3 * CDIM];   // qkv (half)
__device__ __half g_attn[TOKG * CDIM];       // attention out (half)
__device__ float  g_x2  [TOKG * CDIM];       // x + attn (float)
__device__ __half g_xn2 [TOKG * CDIM];       // LN2 out (half)
__device__ __half g_hid [TOKG * MLPD];       // MLP hidden (half)
__device__ __half g_wqkvT[3 * CDIM * CDIM];  // transposed half weights [n][k]
__device__ __half g_wprojT[CDIM * CDIM];
__device__ __half g_w1T  [MLPD * CDIM];
__device__ __half g_w2T  [CDIM * MLPD];

// ---------------- helpers ----------------
__device__ __forceinline__ void win_map(int row, int& gidx, bool& valid) {
    int n  = row / HW, t = row % HW;
    int bb = n / NWINB, nw = n % NWINB;
    int wh = nw / NWIN1, ww = nw % NWIN1;
    int ii = t / WIN,    jj = t % WIN;
    int gh = wh * WIN + ii, gw = ww * WIN + jj;
    valid = (gh < HT) && (gw < WT);
    gidx  = (bb * HT + gh) * WT + gw;
}
__device__ __forceinline__ uint32_t smem_u32(const void* p) {
    return (uint32_t)__cvta_generic_to_shared(p);
}
__device__ __forceinline__ void cp16(uint32_t dst, const void* src) {
    asm volatile("cp.async.cg.shared.global [%0], [%1], 16;\n"
                 :: "r"(dst), "l"(src));
}
__device__ __forceinline__ void ldsm4(uint32_t& r0, uint32_t& r1,
                                      uint32_t& r2, uint32_t& r3, uint32_t a) {
    asm volatile("ldmatrix.sync.aligned.m8n8.x4.shared.b16 {%0,%1,%2,%3}, [%4];"
                 : "=r"(r0), "=r"(r1), "=r"(r2), "=r"(r3) : "r"(a));
}
__device__ __forceinline__ void mma16816(float* c, const uint32_t* a,
                                         const uint32_t* b) {
    asm volatile(
        "mma.sync.aligned.m16n8k16.row.col.f32.f16.f16.f32 "
        "{%0,%1,%2,%3}, {%4,%5,%6,%7}, {%8,%9}, {%0,%1,%2,%3};\n"
        : "+f"(c[0]), "+f"(c[1]), "+f"(c[2]), "+f"(c[3])
        : "r"(a[0]), "r"(a[1]), "r"(a[2]), "r"(a[3]),
          "r"(b[0]), "r"(b[1]));
}

// ---------------- merged weight transpose + fp32->fp16 (one launch) ---------
// tiles: qkv 72x24=1728, proj 24x24=576, w1 96x24=2304, w2 24x96=2304 -> 6912
__global__ __launch_bounds__(256) void f2hT_all_kernel(
    const float* __restrict__ w_qkv, const float* __restrict__ w_proj,
    const float* __restrict__ w1,    const float* __restrict__ w2)
{
    __shared__ float t[32][33];
    int tile = blockIdx.x;
    const float* src; __half* dst; int K, N, bx, by;
    if (tile < 1728)      { src = w_qkv;  dst = g_wqkvT;  K = CDIM; N = 3*CDIM;
                            bx = tile % 72; by = tile / 72; }
    else if (tile < 2304) { tile -= 1728; src = w_proj; dst = g_wprojT;
                            K = CDIM; N = CDIM; bx = tile % 24; by = tile / 24; }
    else if (tile < 4608) { tile -= 2304; src = w1; dst = g_w1T;
                            K = CDIM; N = MLPD; bx = tile % 96; by = tile / 96; }
    else                  { tile -= 4608; src = w2; dst = g_w2T;
                            K = MLPD; N = CDIM; bx = tile % 24; by = tile / 24; }
    int n0 = bx * 32, k0 = by * 32;
    int tx = threadIdx.x, ty = threadIdx.y;
    #pragma unroll
    for (int i = 0; i < 32; i += 8)
        t[ty + i][tx] = src[(size_t)(k0 + ty + i) * N + n0 + tx];
    __syncthreads();
    #pragma unroll
    for (int i = 0; i < 32; i += 8)
        dst[(size_t)(n0 + ty + i) * K + k0 + tx] = __float2half_rn(t[tx][ty + i]);
}

// ---------------- LayerNorm: warp-per-row, no smem/barriers -----------------
__global__ __launch_bounds__(256) void ln_kernel(
    const float* __restrict__ in, __half* __restrict__ outp,
    const float* __restrict__ g, const float* __restrict__ b)
{
    int warp = threadIdx.x >> 5, lane = threadIdx.x & 31;
    int row  = blockIdx.x * 8 + warp;
    const float* xr = in + (size_t)row * CDIM;
    __half* orow = outp + (size_t)row * CDIM;

    float4 v[6];
    float s = 0.f, sq = 0.f;
    #pragma unroll
    for (int j = 0; j < 6; j++) {
        v[j] = *(const float4*)&xr[j * 128 + lane * 4];
        s  += v[j].x + v[j].y + v[j].z + v[j].w;
        sq += v[j].x * v[j].x + v[j].y * v[j].y
            + v[j].z * v[j].z + v[j].w * v[j].w;
    }
    #pragma unroll
    for (int off = 16; off; off >>= 1) {
        s  += __shfl_xor_sync(~0u, s,  off);
        sq += __shfl_xor_sync(~0u, sq, off);
    }
    float mean = s * (1.f / CDIM);
    float var  = sq * (1.f / CDIM) - mean * mean;
    float rstd = rsqrtf(var + EPS);
    #pragma unroll
    for (int j = 0; j < 6; j++) {
        int c = j * 128 + lane * 4;
        float4 g4 = *(const float4*)&g[c];
        float4 b4 = *(const float4*)&b[c];
        __half2 h0 = __floats2half2_rn((v[j].x - mean) * rstd * g4.x + b4.x,
                                       (v[j].y - mean) * rstd * g4.y + b4.y);
        __half2 h1 = __floats2half2_rn((v[j].z - mean) * rstd * g4.z + b4.z,
                                       (v[j].w - mean) * rstd * g4.w + b4.w);
        *(__half2*)&orow[c]     = h0;
        *(__half2*)&orow[c + 2] = h1;
    }
}

// ---------------- FP16 GEMM: KTILE=32, 3-stage cp.async (R7/R8 winner) ------
// C[M,N] = A[M,K](half) @ Bt[N,K](half)^T + bias.  M % 128 == 0.
// mode 0: half store   1: exact GELU -> half   2: acc+bias+res -> float
#define KTILE 32
#define AST   40                      // halfs per row (32 + 8 pad)
#define STG_H (128 * AST)             // halfs per stage
#define STG_B (STG_H * 2)             // bytes per stage (10240)
#define GSMEM (6 * STG_B)

__global__ __launch_bounds__(256, 2) void hgemm_kernel(
    const __half* __restrict__ A, const __half* __restrict__ Bt,
    const float* __restrict__ bias, const float* __restrict__ res,
    float* __restrict__ Cf, __half* __restrict__ Ch,
    int M, int N, int K, int mode)
{
    extern __shared__ __half shh[];
    __half* AsS = shh;
    __half* BsS = shh + 3 * STG_H;

    int tid  = threadIdx.x;
    int warp = tid >> 5, lane = tid & 31;
    int wm = warp >> 2, wn = warp & 3;   // 2x4 warps, warp tile 64x32
    int gq = lane >> 2, tr = lane & 3;
    int bm = blockIdx.y * 128, bn = blockIdx.x * 128;

    int srow = tid >> 1;
    int scol = (tid & 1) * 16;
    const __half* Ag = A  + (size_t)(bm + srow) * K + scol;
    const __half* Bg = Bt + (size_t)(bn + srow) * K + scol;
    uint32_t as_st = smem_u32(AsS + srow * AST + scol);
    uint32_t bs_st = smem_u32(BsS + srow * AST + scol);

    uint32_t as_base = smem_u32(AsS);
    uint32_t bs_base = smem_u32(BsS);
    int fr = lane & 15;
    int fc = (lane >> 4) * 8;

    float acc[4][4][4];
    #pragma unroll
    for (int mi = 0; mi < 4; mi++)
        #pragma unroll
        for (int ni = 0; ni < 4; ni++)
            #pragma unroll
            for (int r = 0; r < 4; r++) acc[mi][ni][r] = 0.f;

    int T = K / KTILE;

    #define FILL(t, s) do {                                        \
        const __half* ag_ = Ag + (t) * KTILE;                      \
        uint32_t ad_ = as_st + (s) * STG_B;                        \
        cp16(ad_,      ag_);                                       \
        cp16(ad_ + 16, ag_ + 8);                                   \
        const __half* bg_ = Bg + (t) * KTILE;                      \
        uint32_t bd_ = bs_st + (s) * STG_B;                        \
        cp16(bd_,      bg_);                                       \
        cp16(bd_ + 16, bg_ + 8);                                   \
        asm volatile("cp.async.commit_group;\n");                  \
    } while (0)

    FILL(0, 0);
    FILL(1, 1);

    int s = 0;
    for (int t = 0; t < T; t++) {
        if (t + 1 < T) asm volatile("cp.async.wait_group 1;\n");
        else           asm volatile("cp.async.wait_group 0;\n");
        __syncthreads();
        if (t + 2 < T) {
            int sf = (s == 0) ? 2 : s - 1;
            FILL(t + 2, sf);
        }

        uint32_t ab = as_base + s * STG_B;
        uint32_t bb = bs_base + s * STG_B;
        #pragma unroll
        for (int kk = 0; kk < KTILE; kk += 16) {
            uint32_t af[4][4], bf[4][2];
            #pragma unroll
            for (int mi = 0; mi < 4; mi++) {
                uint32_t addr = ab +
                    (((wm * 64 + mi * 16 + fr) * AST) + kk + fc) * 2;
                ldsm4(af[mi][0], af[mi][1], af[mi][2], af[mi][3], addr);
            }
            #pragma unroll
            for (int nh = 0; nh < 2; nh++) {
                uint32_t addr = bb +
                    (((wn * 32 + nh * 16 + fr) * AST) + kk + fc) * 2;
                ldsm4(bf[2 * nh][0], bf[2 * nh + 1][0],
                      bf[2 * nh][1], bf[2 * nh + 1][1], addr);
            }
            #pragma unroll
            for (int mi = 0; mi < 4; mi++)
                #pragma unroll
                for (int ni = 0; ni < 4; ni++)
                    mma16816(acc[mi][ni], af[mi], bf[ni]);
        }
        s = (s == 2) ? 0 : s + 1;
    }
    #undef FILL

    // ---------------- epilogue ----------------
    #pragma unroll
    for (int mi = 0; mi < 4; mi++) {
        int rbase = bm + wm * 64 + mi * 16 + gq;
        #pragma unroll
        for (int h = 0; h < 2; h++) {
            int row = rbase + 8 * h;
            #pragma unroll
            for (int ni = 0; ni < 4; ni++) {
                int col = bn + wn * 32 + ni * 8 + tr * 2;
                float v0 = acc[mi][ni][2 * h]     + bias[col];
                float v1 = acc[mi][ni][2 * h + 1] + bias[col + 1];
                if (mode == 0) {
                    *(__half2*)&Ch[(size_t)row * N + col] =
                        __floats2half2_rn(v0, v1);
                } else if (mode == 1) {
                    v0 = 0.5f * v0 * (1.f + erff(v0 * 0.70710678118654752f));
                    v1 = 0.5f * v1 * (1.f + erff(v1 * 0.70710678118654752f));
                    *(__half2*)&Ch[(size_t)row * N + col] =
                        __floats2half2_rn(v0, v1);
                } else {
                    Cf[(size_t)row * N + col]     = v0 + res[(size_t)row * N + col];
                    Cf[(size_t)row * N + col + 1] = v1 + res[(size_t)row * N + col + 1];
                }
            }
        }
    }
}

// ---------------- tensor-core window attention (gathers via gtab) -----------
#define QKS   72
#define VPS   216
#define SSX   212
#define F_S   0
#define F_BH  (64 * SSX)
#define F_BW  (F_BH + HW * WIN)
#define F_RH  (F_BW + HW * WIN)
#define F_RW  (F_RH + 27 * HD)
#define F_GT  (F_RW + 27 * HD)          // gtab[196] (ints)
#define F_TOT (F_GT + HW)
#define H_Q   0
#define H_K   (HW * QKS)
#define H_VT  (H_K + HW * QKS)
#define H_P   (H_VT + HD * VPS)
#define H_TOT (H_P + 64 * VPS)
#define ATTN_SMEM_BYTES (F_TOT * 4 + H_TOT * 2)

__global__ __launch_bounds__(256, 1) void attn_kernel(
    const float* __restrict__ rel_h, const float* __restrict__ rel_w,
    const float* __restrict__ b_qkv)
{
    extern __shared__ float smf[];
    float* Ss = smf + F_S;
    float* bh = smf + F_BH;
    float* bw = smf + F_BW;
    float* rhs = smf + F_RH;
    float* rws = smf + F_RW;
    int*   gtab = (int*)(smf + F_GT);
    __half* hbase = (__half*)(smf + F_TOT);
    __half* qs  = hbase + H_Q;
    __half* kss = hbase + H_K;
    __half* vts = hbase + H_VT;
    __half* ps  = hbase + H_P;

    int w0   = blockIdx.x;
    int head = blockIdx.y;
    int tid  = threadIdx.x;
    int warp = tid >> 5, lane = tid & 31;
    int gq = lane >> 2, tr = lane & 3;
    int fr = lane & 15;
    int fc = (lane >> 4) * 8;

    uint32_t qs_b  = smem_u32(qs);
    uint32_t ks_b  = smem_u32(kss);
    uint32_t vt_b  = smem_u32(vts);
    uint32_t ps_b  = smem_u32(ps);

    if (tid < HW) {
        int gi; bool v;
        win_map(w0 * HW + tid, gi, v);
        gtab[tid] = v ? gi : -1;
    }
    for (int idx = tid; idx < 27 * HD; idx += 256) {
        rhs[idx] = rel_h[idx];
        rws[idx] = rel_w[idx];
    }
    __syncthreads();

    const float* bq = b_qkv + head * HD;
    for (int idx = tid; idx < HW * 16; idx += 256) {
        int row = idx >> 4, d = (idx & 15) * 4;
        int gi = gtab[row];
        if (gi >= 0) {
            const __half* src = g_qkv + (size_t)gi * (3 * CDIM) + head * HD + d;
            *(uint2*)&qs [row * QKS + d] = *(const uint2*)(src);
            *(uint2*)&kss[row * QKS + d] = *(const uint2*)(src + CDIM);
        } else {
            #pragma unroll
            for (int j = 0; j < 4; j++) {
                qs [row * QKS + d + j] = __float2half_rn(bq[d + j]);
                kss[row * QKS + d + j] = __float2half_rn(bq[CDIM + d + j]);
            }
        }
    }
    for (int idx = tid; idx < HW * HD; idx += 256) {
        int key = idx >> 6, d = idx & 63;
        int gi = gtab[key];
        vts[d * VPS + key] = (gi >= 0)
            ? g_qkv[(size_t)gi * (3 * CDIM) + 2 * CDIM + head * HD + d]
            : __float2half_rn(bq[2 * CDIM + d]);
    }
    for (int idx = tid; idx < HD * 12; idx += 256) {
        int d = idx / 12;
        vts[d * VPS + HW + idx % 12] = __float2half_rn(0.f);
    }
    __syncthreads();

    for (int j = tid; j < HW * 28; j += 256) {
        int q = j / 28, wch = j % 28;
        int hq = q / WIN, wq = q % WIN;
        const float* tab;
        int o;
        if (wch < 14) { tab = rhs; o = (hq - wch + (WIN - 1)) * HD; }
        else          { tab = rws; o = (wq - (wch - 14) + (WIN - 1)) * HD; }
        float acc = 0.f;
        #pragma unroll
        for (int d = 0; d < HD; d += 4) {
            uint2 hv = *(const uint2*)&qs[q * QKS + d];
            float2 f0 = __half22float2(*(__half2*)&hv.x);
            float2 f1 = __half22float2(*(__half2*)&hv.y);
            float4 t4 = *(const float4*)&tab[o + d];
            acc += f0.x * t4.x + f0.y * t4.y + f1.x * t4.z + f1.y * t4.w;
        }
        if (wch < 14) bh[q * WIN + wch] = acc;
        else          bw[q * WIN + wch - 14] = acc;
    }
    __syncthreads();

    int stripe = warp >> 1, nh = warp & 1;
    int ngr   = nh ? 6 : 7;
    int nbase = nh ? 112 : 0;

    for (int c = 0; c < 4; c++) {
        int q0 = c * 64;
        int rows = (HW - q0 < 64) ? (HW - q0) : 64;
        int nstripes = (rows + 15) >> 4;

        if (stripe < nstripes) {
            int mrow = q0 + stripe * 16;
            float sacc[7][2][4];
            #pragma unroll
            for (int g = 0; g < 7; g++)
                #pragma unroll
                for (int u = 0; u < 2; u++)
                    #pragma unroll
                    for (int r = 0; r < 4; r++) sacc[g][u][r] = 0.f;

            #pragma unroll
            for (int kk = 0; kk < HD; kk += 16) {
                uint32_t af[4];
                int ar = mrow + fr; if (ar > HW - 1) ar = HW - 1;
                ldsm4(af[0], af[1], af[2], af[3],
                      qs_b + (ar * QKS + kk + fc) * 2);
                for (int g = 0; g < ngr; g++) {
                    int br = nbase + g * 16 + fr; if (br > HW - 1) br = HW - 1;
                    uint32_t bf0[2], bf1[2];
                    ldsm4(bf0[0], bf1[0], bf0[1], bf1[1],
                          ks_b + (br * QKS + kk + fc) * 2);
                    mma16816(sacc[g][0], af, bf0);
                    mma16816(sacc[g][1], af, bf1);
                }
            }
            for (int g = 0; g < ngr; g++) {
                #pragma unroll
                for (int u = 0; u < 2; u++) {
                    int col = nbase + g * 16 + u * 8 + tr * 2;
                    int r0 = stripe * 16 + gq;
                    *(float2*)&Ss[r0 * SSX + col] =
                        make_float2(sacc[g][u][0], sacc[g][u][1]);
                    *(float2*)&Ss[(r0 + 8) * SSX + col] =
                        make_float2(sacc[g][u][2], sacc[g][u][3]);
                }
            }
        }
        __syncthreads();

        for (int r = warp; r < rows; r += 8) {
            int q = q0 + r;
            float v[7];
            float mx = -1e30f;
            #pragma unroll
            for (int i = 0; i < 7; i++) {
                int col = lane + 32 * i;
                if (col < HW) {
                    float sv = Ss[r * SSX + col] * 0.125f
                             + bh[q * WIN + col / WIN]
                             + bw[q * WIN + col % WIN];
                    v[i] = sv;
                    mx = fmaxf(mx, sv);
                } else v[i] = -1e30f;
            }
            #pragma unroll
            for (int off = 16; off; off >>= 1)
                mx = fmaxf(mx, __shfl_xor_sync(~0u, mx, off));
            float sum = 0.f;
            #pragma unroll
            for (int i = 0; i < 7; i++) {
                int col = lane + 32 * i;
                if (col < HW) { float e = __expf(v[i] - mx); v[i] = e; sum += e; }
                else v[i] = 0.f;
            }
            #pragma unroll
            for (int off = 16; off; off >>= 1)
                sum += __shfl_xor_sync(~0u, sum, off);
            float inv = 1.f / sum;
            #pragma unroll
            for (int i = 0; i < 7; i++) {
                int col = lane + 32 * i;
                if (col < HW)       ps[r * VPS + col] = __float2half_rn(v[i] * inv);
                else if (col < 208) ps[r * VPS + col] = __float2half_rn(0.f);
            }
        }
        __syncthreads();

        if (stripe < nstripes) {
            int d0b = nh * 32;
            float oacc[4][4];
            #pragma unroll
            for (int ni = 0; ni < 4; ni++)
                #pragma unroll
                for (int r = 0; r < 4; r++) oacc[ni][r] = 0.f;

            for (int kk = 0; kk < 208; kk += 16) {
                uint32_t af[4];
                ldsm4(af[0], af[1], af[2], af[3],
                      ps_b + ((stripe * 16 + fr) * VPS + kk + fc) * 2);
                #pragma unroll
                for (int g = 0; g < 2; g++) {
                    uint32_t bf0[2], bf1[2];
                    ldsm4(bf0[0], bf1[0], bf0[1], bf1[1],
                          vt_b + ((d0b + g * 16 + fr) * VPS + kk + fc) * 2);
                    mma16816(oacc[2 * g],     af, bf0);
                    mma16816(oacc[2 * g + 1], af, bf1);
                }
            }
            #pragma unroll
            for (int ni = 0; ni < 4; ni++) {
                int col = head * HD + d0b + ni * 8 + tr * 2;
                #pragma unroll
                for (int h = 0; h < 2; h++) {
                    int grow = q0 + stripe * 16 + gq + 8 * h;
                    if (grow < HW) {
                        int gi = gtab[grow];
                        if (gi >= 0) {
                            __half* op = g_attn + (size_t)gi * CDIM + col;
                            *(__half2*)op = __floats2half2_rn(oacc[ni][2 * h],
                                                              oacc[ni][2 * h + 1]);
                        }
                    }
                }
            }
        }
        __syncthreads();
    }
}

// ---------------- launcher ----------------
extern "C" void kernel_launch(void* const* d_in, const int* in_sizes, int n_in,
                              void* d_out, int out_size)
{
    const float* x      = (const float*)d_in[0];
    const float* g1     = (const float*)d_in[1];
    const float* b1     = (const float*)d_in[2];
    const float* w_qkv  = (const float*)d_in[3];
    const float* b_qkv  = (const float*)d_in[4];
    const float* w_proj = (const float*)d_in[5];
    const float* b_proj = (const float*)d_in[6];
    const float* rel_h  = (const float*)d_in[7];
    const float* rel_w  = (const float*)d_in[8];
    const float* g2     = (const float*)d_in[9];
    const float* b2     = (const float*)d_in[10];
    const float* w1     = (const float*)d_in[11];
    const float* b1m    = (const float*)d_in[12];
    const float* w2     = (const float*)d_in[13];
    const float* b2m    = (const float*)d_in[14];
    float* out = (float*)d_out;

    __half *p_xn1, *p_qkv, *p_attn, *p_xn2, *p_hid;
    __half *p_wqkvT, *p_wprojT, *p_w1T, *p_w2T;
    float *p_x2;
    cudaGetSymbolAddress((void**)&p_xn1,   g_xn1);
    cudaGetSymbolAddress((void**)&p_qkv,   g_qkv);
    cudaGetSymbolAddress((void**)&p_attn,  g_attn);
    cudaGetSymbolAddress((void**)&p_x2,    g_x2);
    cudaGetSymbolAddress((void**)&p_xn2,   g_xn2);
    cudaGetSymbolAddress((void**)&p_hid,   g_hid);
    cudaGetSymbolAddress((void**)&p_wqkvT, g_wqkvT);
    cudaGetSymbolAddress((void**)&p_wprojT,g_wprojT);
    cudaGetSymbolAddress((void**)&p_w1T,   g_w1T);
    cudaGetSymbolAddress((void**)&p_w2T,   g_w2T);

    static int attr_set = 0;
    if (!attr_set) {
        cudaFuncSetAttribute(attn_kernel,
            cudaFuncAttributeMaxDynamicSharedMemorySize, ATTN_SMEM_BYTES);
        cudaFuncSetAttribute(hgemm_kernel,
            cudaFuncAttributeMaxDynamicSharedMemorySize, GSMEM);
        attr_set = 1;
    }

    // 0) all weight transposes in one launch (6912 tiles)
    f2hT_all_kernel<<<6912, dim3(32, 8)>>>(w_qkv, w_proj, w1, w2);

    // 1) LN1 (warp-per-row) -> g_xn1 (half)
    ln_kernel<<<TOKG / 8, 256>>>(x, p_xn1, g1, b1);

    // 2) QKV GEMM: [8192,768] @ [768,2304] -> g_qkv (half)
    {
        dim3 grid((3 * CDIM) / 128, TOKG / 128);
        hgemm_kernel<<<grid, 256, GSMEM>>>(p_xn1, p_wqkvT, b_qkv, nullptr,
                                           nullptr, p_qkv,
                                           TOKG, 3 * CDIM, CDIM, 0);
    }

    // 3) tensor-core attention (window gather) -> g_attn (half, global layout)
    attn_kernel<<<dim3(NW, NHEAD), 256, ATTN_SMEM_BYTES>>>(rel_h, rel_w, b_qkv);

    // 4) proj GEMM + residual(x) -> g_x2 (float)
    {
        dim3 grid(CDIM / 128, TOKG / 128);
        hgemm_kernel<<<grid, 256, GSMEM>>>(p_attn, p_wprojT, b_proj, x,
                                           p_x2, nullptr,
                                           TOKG, CDIM, CDIM, 2);
    }

    // 5) LN2 (warp-per-row) -> g_xn2 (half)
    ln_kernel<<<TOKG / 8, 256>>>(p_x2, p_xn2, g2, b2);

    // 6) FC1 + GELU -> g_hid (half)
    {
        dim3 grid(MLPD / 128, TOKG / 128);
        hgemm_kernel<<<grid, 256, GSMEM>>>(p_xn2, p_w1T, b1m, nullptr,
                                           nullptr, p_hid,
                                           TOKG, MLPD, CDIM, 1);
    }

    // 7) FC2 + residual(g_x2) -> out (float)
    {
        dim3 grid(CDIM / 128, TOKG / 128);
        hgemm_kernel<<<grid, 256, GSMEM>>>(p_hid, p_w2T, b2m, p_x2,
                                           out, nullptr,
                                           TOKG, CDIM, MLPD, 2);
    }
}

// round 15
// speedup vs baseline: 1.5449x; 1.3142x over previous
#include <cuda_runtime.h>
#include <cuda_fp16.h>
#include <math.h>
#include <stdint.h>

// ---------------- problem constants ----------------
#define BATCH   2
#define HT      64
#define WT      64
#define CDIM    768
#define WIN     14
#define NWIN1   5
#define NWINB   25
#define NW      50
#define HW      196
#define NHEAD   12
#define HD      64
#define MLPD    3072
#define TOKG    (BATCH*HT*WT)  // 8192 global tokens
#define EPS     1e-5f

// ---------------- scratch (global token layout everywhere) ----------------
__device__ __half g_xn1 [TOKG * CDIM];       // LN1 out (half)
__device__ __half g_qkv [TOKG * 3 * CDIM];   // qkv (half)
__device__ __half g_attn[TOKG * CDIM];       // attention out (half)
__device__ float  g_x2  [TOKG * CDIM];       // x + attn (float)
__device__ __half g_xn2 [TOKG * CDIM];       // LN2 out (half)
__device__ __half g_hid [TOKG * MLPD];       // MLP hidden (half)
__device__ __half g_wqkvT[3 * CDIM * CDIM];  // transposed half weights [n][k]
__device__ __half g_wprojT[CDIM * CDIM];
__device__ __half g_w1T  [MLPD * CDIM];
__device__ __half g_w2T  [CDIM * MLPD];

// ---------------- helpers ----------------
__device__ __forceinline__ void win_map(int row, int& gidx, bool& valid) {
    int n  = row / HW, t = row % HW;
    int bb = n / NWINB, nw = n % NWINB;
    int wh = nw / NWIN1, ww = nw % NWIN1;
    int ii = t / WIN,    jj = t % WIN;
    int gh = wh * WIN + ii, gw = ww * WIN + jj;
    valid = (gh < HT) && (gw < WT);
    gidx  = (bb * HT + gh) * WT + gw;
}
__device__ __forceinline__ uint32_t smem_u32(const void* p) {
    return (uint32_t)__cvta_generic_to_shared(p);
}
__device__ __forceinline__ void cp16(uint32_t dst, const void* src) {
    asm volatile("cp.async.cg.shared.global [%0], [%1], 16;\n"
                 :: "r"(dst), "l"(src));
}
__device__ __forceinline__ void ldsm4(uint32_t& r0, uint32_t& r1,
                                      uint32_t& r2, uint32_t& r3, uint32_t a) {
    asm volatile("ldmatrix.sync.aligned.m8n8.x4.shared.b16 {%0,%1,%2,%3}, [%4];"
                 : "=r"(r0), "=r"(r1), "=r"(r2), "=r"(r3) : "r"(a));
}
__device__ __forceinline__ void mma16816(float* c, const uint32_t* a,
                                         const uint32_t* b) {
    asm volatile(
        "mma.sync.aligned.m16n8k16.row.col.f32.f16.f16.f32 "
        "{%0,%1,%2,%3}, {%4,%5,%6,%7}, {%8,%9}, {%0,%1,%2,%3};\n"
        : "+f"(c[0]), "+f"(c[1]), "+f"(c[2]), "+f"(c[3])
        : "r"(a[0]), "r"(a[1]), "r"(a[2]), "r"(a[3]),
          "r"(b[0]), "r"(b[1]));
}

// ---------------- merged weight transpose + fp32->fp16 (one launch) ---------
__global__ __launch_bounds__(256) void f2hT_all_kernel(
    const float* __restrict__ w_qkv, const float* __restrict__ w_proj,
    const float* __restrict__ w1,    const float* __restrict__ w2)
{
    __shared__ float t[32][33];
    int tile = blockIdx.x;
    const float* src; __half* dst; int K, N, bx, by;
    if (tile < 1728)      { src = w_qkv;  dst = g_wqkvT;  K = CDIM; N = 3*CDIM;
                            bx = tile % 72; by = tile / 72; }
    else if (tile < 2304) { tile -= 1728; src = w_proj; dst = g_wprojT;
                            K = CDIM; N = CDIM; bx = tile % 24; by = tile / 24; }
    else if (tile < 4608) { tile -= 2304; src = w1; dst = g_w1T;
                            K = CDIM; N = MLPD; bx = tile % 96; by = tile / 96; }
    else                  { tile -= 4608; src = w2; dst = g_w2T;
                            K = MLPD; N = CDIM; bx = tile % 24; by = tile / 24; }
    int n0 = bx * 32, k0 = by * 32;
    int tx = threadIdx.x, ty = threadIdx.y;
    #pragma unroll
    for (int i = 0; i < 32; i += 8)
        t[ty + i][tx] = src[(size_t)(k0 + ty + i) * N + n0 + tx];
    __syncthreads();
    #pragma unroll
    for (int i = 0; i < 32; i += 8)
        dst[(size_t)(n0 + ty + i) * K + k0 + tx] = __float2half_rn(t[tx][ty + i]);
}

// ---------------- LayerNorm: warp-per-row, no smem/barriers -----------------
__global__ __launch_bounds__(256) void ln_kernel(
    const float* __restrict__ in, __half* __restrict__ outp,
    const float* __restrict__ g, const float* __restrict__ b)
{
    int warp = threadIdx.x >> 5, lane = threadIdx.x & 31;
    int row  = blockIdx.x * 8 + warp;
    const float* xr = in + (size_t)row * CDIM;
    __half* orow = outp + (size_t)row * CDIM;

    float4 v[6];
    float s = 0.f, sq = 0.f;
    #pragma unroll
    for (int j = 0; j < 6; j++) {
        v[j] = *(const float4*)&xr[j * 128 + lane * 4];
        s  += v[j].x + v[j].y + v[j].z + v[j].w;
        sq += v[j].x * v[j].x + v[j].y * v[j].y
            + v[j].z * v[j].z + v[j].w * v[j].w;
    }
    #pragma unroll
    for (int off = 16; off; off >>= 1) {
        s  += __shfl_xor_sync(~0u, s,  off);
        sq += __shfl_xor_sync(~0u, sq, off);
    }
    float mean = s * (1.f / CDIM);
    float var  = sq * (1.f / CDIM) - mean * mean;
    float rstd = rsqrtf(var + EPS);
    #pragma unroll
    for (int j = 0; j < 6; j++) {
        int c = j * 128 + lane * 4;
        float4 g4 = *(const float4*)&g[c];
        float4 b4 = *(const float4*)&b[c];
        __half2 h0 = __floats2half2_rn((v[j].x - mean) * rstd * g4.x + b4.x,
                                       (v[j].y - mean) * rstd * g4.y + b4.y);
        __half2 h1 = __floats2half2_rn((v[j].z - mean) * rstd * g4.z + b4.z,
                                       (v[j].w - mean) * rstd * g4.w + b4.w);
        *(__half2*)&orow[c]     = h0;
        *(__half2*)&orow[c + 2] = h1;
    }
}

// ---------------- FP16 GEMM: KTILE=32, 3-stage cp.async (R7/R8 winner) ------
#define KTILE 32
#define AST   40
#define STG_H (128 * AST)
#define STG_B (STG_H * 2)
#define GSMEM (6 * STG_B)

__global__ __launch_bounds__(256, 2) void hgemm_kernel(
    const __half* __restrict__ A, const __half* __restrict__ Bt,
    const float* __restrict__ bias, const float* __restrict__ res,
    float* __restrict__ Cf, __half* __restrict__ Ch,
    int M, int N, int K, int mode)
{
    extern __shared__ __half shh[];
    __half* AsS = shh;
    __half* BsS = shh + 3 * STG_H;

    int tid  = threadIdx.x;
    int warp = tid >> 5, lane = tid & 31;
    int wm = warp >> 2, wn = warp & 3;
    int gq = lane >> 2, tr = lane & 3;
    int bm = blockIdx.y * 128, bn = blockIdx.x * 128;

    int srow = tid >> 1;
    int scol = (tid & 1) * 16;
    const __half* Ag = A  + (size_t)(bm + srow) * K + scol;
    const __half* Bg = Bt + (size_t)(bn + srow) * K + scol;
    uint32_t as_st = smem_u32(AsS + srow * AST + scol);
    uint32_t bs_st = smem_u32(BsS + srow * AST + scol);

    uint32_t as_base = smem_u32(AsS);
    uint32_t bs_base = smem_u32(BsS);
    int fr = lane & 15;
    int fc = (lane >> 4) * 8;

    float acc[4][4][4];
    #pragma unroll
    for (int mi = 0; mi < 4; mi++)
        #pragma unroll
        for (int ni = 0; ni < 4; ni++)
            #pragma unroll
            for (int r = 0; r < 4; r++) acc[mi][ni][r] = 0.f;

    int T = K / KTILE;

    #define FILL(t, s) do {                                        \
        const __half* ag_ = Ag + (t) * KTILE;                      \
        uint32_t ad_ = as_st + (s) * STG_B;                        \
        cp16(ad_,      ag_);                                       \
        cp16(ad_ + 16, ag_ + 8);                                   \
        const __half* bg_ = Bg + (t) * KTILE;                      \
        uint32_t bd_ = bs_st + (s) * STG_B;                        \
        cp16(bd_,      bg_);                                       \
        cp16(bd_ + 16, bg_ + 8);                                   \
        asm volatile("cp.async.commit_group;\n");                  \
    } while (0)

    FILL(0, 0);
    FILL(1, 1);

    int s = 0;
    for (int t = 0; t < T; t++) {
        if (t + 1 < T) asm volatile("cp.async.wait_group 1;\n");
        else           asm volatile("cp.async.wait_group 0;\n");
        __syncthreads();
        if (t + 2 < T) {
            int sf = (s == 0) ? 2 : s - 1;
            FILL(t + 2, sf);
        }

        uint32_t ab = as_base + s * STG_B;
        uint32_t bb = bs_base + s * STG_B;
        #pragma unroll
        for (int kk = 0; kk < KTILE; kk += 16) {
            uint32_t af[4][4], bf[4][2];
            #pragma unroll
            for (int mi = 0; mi < 4; mi++) {
                uint32_t addr = ab +
                    (((wm * 64 + mi * 16 + fr) * AST) + kk + fc) * 2;
                ldsm4(af[mi][0], af[mi][1], af[mi][2], af[mi][3], addr);
            }
            #pragma unroll
            for (int nh = 0; nh < 2; nh++) {
                uint32_t addr = bb +
                    (((wn * 32 + nh * 16 + fr) * AST) + kk + fc) * 2;
                ldsm4(bf[2 * nh][0], bf[2 * nh + 1][0],
                      bf[2 * nh][1], bf[2 * nh + 1][1], addr);
            }
            #pragma unroll
            for (int mi = 0; mi < 4; mi++)
                #pragma unroll
                for (int ni = 0; ni < 4; ni++)
                    mma16816(acc[mi][ni], af[mi], bf[ni]);
        }
        s = (s == 2) ? 0 : s + 1;
    }
    #undef FILL

    #pragma unroll
    for (int mi = 0; mi < 4; mi++) {
        int rbase = bm + wm * 64 + mi * 16 + gq;
        #pragma unroll
        for (int h = 0; h < 2; h++) {
            int row = rbase + 8 * h;
            #pragma unroll
            for (int ni = 0; ni < 4; ni++) {
                int col = bn + wn * 32 + ni * 8 + tr * 2;
                float v0 = acc[mi][ni][2 * h]     + bias[col];
                float v1 = acc[mi][ni][2 * h + 1] + bias[col + 1];
                if (mode == 0) {
                    *(__half2*)&Ch[(size_t)row * N + col] =
                        __floats2half2_rn(v0, v1);
                } else if (mode == 1) {
                    v0 = 0.5f * v0 * (1.f + erff(v0 * 0.70710678118654752f));
                    v1 = 0.5f * v1 * (1.f + erff(v1 * 0.70710678118654752f));
                    *(__half2*)&Ch[(size_t)row * N + col] =
                        __floats2half2_rn(v0, v1);
                } else {
                    Cf[(size_t)row * N + col]     = v0 + res[(size_t)row * N + col];
                    Cf[(size_t)row * N + col + 1] = v1 + res[(size_t)row * N + col + 1];
                }
            }
        }
    }
}

// ---------------- tensor-core window attention ------------------------------
// Bias tables via MMA; V staging vectorized.
#define QKS   72
#define VPS   216
#define SSX   212
#define BFS   34
#define F_S   0
#define F_BH  (64 * SSX)                 // bhf[196][34] fp32
#define F_BW  (F_BH + HW * BFS)          // bwf[196][34] fp32
#define F_GT  (F_BW + HW * BFS)          // gtab[196]
#define F_TOT (F_GT + HW)
#define H_Q   0
#define H_K   (HW * QKS)
#define H_VT  (H_K + HW * QKS)
#define H_P   (H_VT + HD * VPS)
#define H_RH  (H_P + 64 * VPS)           // rhh[32][72] half
#define H_RW  (H_RH + 32 * QKS)          // rwh[32][72] half
#define H_TOT (H_RW + 32 * QKS)
#define ATTN_SMEM_BYTES (F_TOT * 4 + H_TOT * 2)

__global__ __launch_bounds__(256, 1) void attn_kernel(
    const float* __restrict__ rel_h, const float* __restrict__ rel_w,
    const float* __restrict__ b_qkv)
{
    extern __shared__ float smf[];
    float* Ss  = smf + F_S;
    float* bhf = smf + F_BH;
    float* bwf = smf + F_BW;
    int*   gtab = (int*)(smf + F_GT);
    __half* hbase = (__half*)(smf + F_TOT);
    __half* qs  = hbase + H_Q;
    __half* kss = hbase + H_K;
    __half* vts = hbase + H_VT;
    __half* ps  = hbase + H_P;
    __half* rhh = hbase + H_RH;
    __half* rwh = hbase + H_RW;

    int w0   = blockIdx.x;
    int head = blockIdx.y;
    int tid  = threadIdx.x;
    int warp = tid >> 5, lane = tid & 31;
    int gq = lane >> 2, tr = lane & 3;
    int fr = lane & 15;
    int fc = (lane >> 4) * 8;

    uint32_t qs_b = smem_u32(qs);
    uint32_t ks_b = smem_u32(kss);
    uint32_t vt_b = smem_u32(vts);
    uint32_t ps_b = smem_u32(ps);
    uint32_t rh_b = smem_u32(rhh);
    uint32_t rw_b = smem_u32(rwh);

    if (tid < HW) {
        int gi; bool v;
        win_map(w0 * HW + tid, gi, v);
        gtab[tid] = v ? gi : -1;
    }
    // rel tables -> half [32][QKS], rows 27..31 zero
    for (int idx = tid; idx < 32 * 16; idx += 256) {
        int rrow = idx >> 4, d4 = (idx & 15) * 4;
        if (rrow < 27) {
            float4 fh = *(const float4*)&rel_h[rrow * HD + d4];
            float4 fw = *(const float4*)&rel_w[rrow * HD + d4];
            *(__half2*)&rhh[rrow * QKS + d4]     = __floats2half2_rn(fh.x, fh.y);
            *(__half2*)&rhh[rrow * QKS + d4 + 2] = __floats2half2_rn(fh.z, fh.w);
            *(__half2*)&rwh[rrow * QKS + d4]     = __floats2half2_rn(fw.x, fw.y);
            *(__half2*)&rwh[rrow * QKS + d4 + 2] = __floats2half2_rn(fw.z, fw.w);
        } else {
            __half2 z = __floats2half2_rn(0.f, 0.f);
            *(__half2*)&rhh[rrow * QKS + d4]     = z;
            *(__half2*)&rhh[rrow * QKS + d4 + 2] = z;
            *(__half2*)&rwh[rrow * QKS + d4]     = z;
            *(__half2*)&rwh[rrow * QKS + d4 + 2] = z;
        }
    }
    __syncthreads();

    // ---- stage Q,K (row-major) and V (transposed), vectorized ----
    const float* bq = b_qkv + head * HD;
    for (int idx = tid; idx < HW * 16; idx += 256) {
        int row = idx >> 4, d = (idx & 15) * 4;
        int gi = gtab[row];
        __half vtmp[4];
        if (gi >= 0) {
            const __half* src = g_qkv + (size_t)gi * (3 * CDIM) + head * HD + d;
            *(uint2*)&qs [row * QKS + d] = *(const uint2*)(src);
            *(uint2*)&kss[row * QKS + d] = *(const uint2*)(src + CDIM);
            *(uint2*)vtmp = *(const uint2*)(src + 2 * CDIM);
        } else {
            #pragma unroll
            for (int j = 0; j < 4; j++) {
                qs [row * QKS + d + j] = __float2half_rn(bq[d + j]);
                kss[row * QKS + d + j] = __float2half_rn(bq[CDIM + d + j]);
                vtmp[j] = __float2half_rn(bq[2 * CDIM + d + j]);
            }
        }
        #pragma unroll
        for (int j = 0; j < 4; j++)
            vts[(d + j) * VPS + row] = vtmp[j];
    }
    for (int idx = tid; idx < HD * 12; idx += 256) {
        int d = idx / 12;
        vts[d * VPS + HW + idx % 12] = __float2half_rn(0.f);
    }
    __syncthreads();

    // ---- bias tables via MMA: bhf[196][27] = Q*RhT, bwf = Q*RwT ----
    for (int st = warp; st < 13; st += 8) {
        float ba[4][4], bb2[4][4];
        #pragma unroll
        for (int g = 0; g < 4; g++)
            #pragma unroll
            for (int r = 0; r < 4; r++) { ba[g][r] = 0.f; bb2[g][r] = 0.f; }
        int mrow = st * 16;
        #pragma unroll
        for (int kk = 0; kk < HD; kk += 16) {
            uint32_t qf[4];
            int ar = mrow + fr; if (ar > HW - 1) ar = HW - 1;
            ldsm4(qf[0], qf[1], qf[2], qf[3], qs_b + (ar * QKS + kk + fc) * 2);
            #pragma unroll
            for (int g = 0; g < 2; g++) {
                uint32_t hf0[2], hf1[2], wf0[2], wf1[2];
                ldsm4(hf0[0], hf1[0], hf0[1], hf1[1],
                      rh_b + ((g * 16 + fr) * QKS + kk + fc) * 2);
                ldsm4(wf0[0], wf1[0], wf0[1], wf1[1],
                      rw_b + ((g * 16 + fr) * QKS + kk + fc) * 2);
                mma16816(ba[2 * g],      qf, hf0);
                mma16816(ba[2 * g + 1],  qf, hf1);
                mma16816(bb2[2 * g],     qf, wf0);
                mma16816(bb2[2 * g + 1], qf, wf1);
            }
        }
        #pragma unroll
        for (int g = 0; g < 4; g++) {
            int col = g * 8 + tr * 2;
            int r0 = mrow + gq;
            if (r0 < HW) {
                *(float2*)&bhf[r0 * BFS + col] = make_float2(ba[g][0], ba[g][1]);
                *(float2*)&bwf[r0 * BFS + col] = make_float2(bb2[g][0], bb2[g][1]);
            }
            if (r0 + 8 < HW) {
                *(float2*)&bhf[(r0 + 8) * BFS + col] = make_float2(ba[g][2], ba[g][3]);
                *(float2*)&bwf[(r0 + 8) * BFS + col] = make_float2(bb2[g][2], bb2[g][3]);
            }
        }
    }
    __syncthreads();

    int stripe = warp >> 1, nh = warp & 1;
    int ngr   = nh ? 6 : 7;
    int nbase = nh ? 112 : 0;

    for (int c = 0; c < 4; c++) {
        int q0 = c * 64;
        int rows = (HW - q0 < 64) ? (HW - q0) : 64;
        int nstripes = (rows + 15) >> 4;

        if (stripe < nstripes) {
            int mrow = q0 + stripe * 16;
            float sacc[7][2][4];
            #pragma unroll
            for (int g = 0; g < 7; g++)
                #pragma unroll
                for (int u = 0; u < 2; u++)
                    #pragma unroll
                    for (int r = 0; r < 4; r++) sacc[g][u][r] = 0.f;

            #pragma unroll
            for (int kk = 0; kk < HD; kk += 16) {
                uint32_t af[4];
                int ar = mrow + fr; if (ar > HW - 1) ar = HW - 1;
                ldsm4(af[0], af[1], af[2], af[3],
                      qs_b + (ar * QKS + kk + fc) * 2);
                for (int g = 0; g < ngr; g++) {
                    int br = nbase + g * 16 + fr; if (br > HW - 1) br = HW - 1;
                    uint32_t bf0[2], bf1[2];
                    ldsm4(bf0[0], bf1[0], bf0[1], bf1[1],
                          ks_b + (br * QKS + kk + fc) * 2);
                    mma16816(sacc[g][0], af, bf0);
                    mma16816(sacc[g][1], af, bf1);
                }
            }
            for (int g = 0; g < ngr; g++) {
                #pragma unroll
                for (int u = 0; u < 2; u++) {
                    int col = nbase + g * 16 + u * 8 + tr * 2;
                    int r0 = stripe * 16 + gq;
                    *(float2*)&Ss[r0 * SSX + col] =
                        make_float2(sacc[g][u][0], sacc[g][u][1]);
                    *(float2*)&Ss[(r0 + 8) * SSX + col] =
                        make_float2(sacc[g][u][2], sacc[g][u][3]);
                }
            }
        }
        __syncthreads();

        for (int r = warp; r < rows; r += 8) {
            int q = q0 + r;
            int hq = q / WIN, wq = q % WIN;
            float v[7];
            float mx = -1e30f;
            #pragma unroll
            for (int i = 0; i < 7; i++) {
                int col = lane + 32 * i;
                if (col < HW) {
                    int kh = col / WIN, kw = col % WIN;
                    float sv = Ss[r * SSX + col] * 0.125f
                             + bhf[q * BFS + (hq - kh + WIN - 1)]
                             + bwf[q * BFS + (wq - kw + WIN - 1)];
                    v[i] = sv;
                    mx = fmaxf(mx, sv);
                } else v[i] = -1e30f;
            }
            #pragma unroll
            for (int off = 16; off; off >>= 1)
                mx = fmaxf(mx, __shfl_xor_sync(~0u, mx, off));
            float sum = 0.f;
            #pragma unroll
            for (int i = 0; i < 7; i++) {
                int col = lane + 32 * i;
                if (col < HW) { float e = __expf(v[i] - mx); v[i] = e; sum += e; }
                else v[i] = 0.f;
            }
            #pragma unroll
            for (int off = 16; off; off >>= 1)
                sum += __shfl_xor_sync(~0u, sum, off);
            float inv = 1.f / sum;
            #pragma unroll
            for (int i = 0; i < 7; i++) {
                int col = lane + 32 * i;
                if (col < HW)       ps[r * VPS + col] = __float2half_rn(v[i] * inv);
                else if (col < 208) ps[r * VPS + col] = __float2half_rn(0.f);
            }
        }
        __syncthreads();

        if (stripe < nstripes) {
            int d0b = nh * 32;
            float oacc[4][4];
            #pragma unroll
            for (int ni = 0; ni < 4; ni++)
                #pragma unroll
                for (int r = 0; r < 4; r++) oacc[ni][r] = 0.f;

            for (int kk = 0; kk < 208; kk += 16) {
                uint32_t af[4];
                ldsm4(af[0], af[1], af[2], af[3],
                      ps_b + ((stripe * 16 + fr) * VPS + kk + fc) * 2);
                #pragma unroll
                for (int g = 0; g < 2; g++) {
                    uint32_t bf0[2], bf1[2];
                    ldsm4(bf0[0], bf1[0], bf0[1], bf1[1],
                          vt_b + ((d0b + g * 16 + fr) * VPS + kk + fc) * 2);
                    mma16816(oacc[2 * g],     af, bf0);
                    mma16816(oacc[2 * g + 1], af, bf1);
                }
            }
            #pragma unroll
            for (int ni = 0; ni < 4; ni++) {
                int col = head * HD + d0b + ni * 8 + tr * 2;
                #pragma unroll
                for (int h = 0; h < 2; h++) {
                    int grow = q0 + stripe * 16 + gq + 8 * h;
                    if (grow < HW) {
                        int gi = gtab[grow];
                        if (gi >= 0) {
                            __half* op = g_attn + (size_t)gi * CDIM + col;
                            *(__half2*)op = __floats2half2_rn(oacc[ni][2 * h],
                                                              oacc[ni][2 * h + 1]);
                        }
                    }
                }
            }
        }
        __syncthreads();
    }
}

// ---------------- launcher ----------------
extern "C" void kernel_launch(void* const* d_in, const int* in_sizes, int n_in,
                              void* d_out, int out_size)
{
    const float* x      = (const float*)d_in[0];
    const float* g1     = (const float*)d_in[1];
    const float* b1     = (const float*)d_in[2];
    const float* w_qkv  = (const float*)d_in[3];
    const float* b_qkv  = (const float*)d_in[4];
    const float* w_proj = (const float*)d_in[5];
    const float* b_proj = (const float*)d_in[6];
    const float* rel_h  = (const float*)d_in[7];
    const float* rel_w  = (const float*)d_in[8];
    const float* g2     = (const float*)d_in[9];
    const float* b2     = (const float*)d_in[10];
    const float* w1     = (const float*)d_in[11];
    const float* b1m    = (const float*)d_in[12];
    const float* w2     = (const float*)d_in[13];
    const float* b2m    = (const float*)d_in[14];
    float* out = (float*)d_out;

    __half *p_xn1, *p_qkv, *p_attn, *p_xn2, *p_hid;
    __half *p_wqkvT, *p_wprojT, *p_w1T, *p_w2T;
    float *p_x2;
    cudaGetSymbolAddress((void**)&p_xn1,   g_xn1);
    cudaGetSymbolAddress((void**)&p_qkv,   g_qkv);
    cudaGetSymbolAddress((void**)&p_attn,  g_attn);
    cudaGetSymbolAddress((void**)&p_x2,    g_x2);
    cudaGetSymbolAddress((void**)&p_xn2,   g_xn2);
    cudaGetSymbolAddress((void**)&p_hid,   g_hid);
    cudaGetSymbolAddress((void**)&p_wqkvT, g_wqkvT);
    cudaGetSymbolAddress((void**)&p_wprojT,g_wprojT);
    cudaGetSymbolAddress((void**)&p_w1T,   g_w1T);
    cudaGetSymbolAddress((void**)&p_w2T,   g_w2T);

    static int attr_set = 0;
    if (!attr_set) {
        cudaFuncSetAttribute(attn_kernel,
            cudaFuncAttributeMaxDynamicSharedMemorySize, ATTN_SMEM_BYTES);
        cudaFuncSetAttribute(hgemm_kernel,
            cudaFuncAttributeMaxDynamicSharedMemorySize, GSMEM);
        attr_set = 1;
    }

    // 0) all weight transposes in one launch
    f2hT_all_kernel<<<6912, dim3(32, 8)>>>(w_qkv, w_proj, w1, w2);

    // 1) LN1 (warp-per-row) -> g_xn1 (half)
    ln_kernel<<<TOKG / 8, 256>>>(x, p_xn1, g1, b1);

    // 2) QKV GEMM -> g_qkv (half)
    {
        dim3 grid((3 * CDIM) / 128, TOKG / 128);
        hgemm_kernel<<<grid, 256, GSMEM>>>(p_xn1, p_wqkvT, b_qkv, nullptr,
                                           nullptr, p_qkv,
                                           TOKG, 3 * CDIM, CDIM, 0);
    }

    // 3) tensor-core attention -> g_attn (half)
    attn_kernel<<<dim3(NW, NHEAD), 256, ATTN_SMEM_BYTES>>>(rel_h, rel_w, b_qkv);

    // 4) proj GEMM + residual(x) -> g_x2 (float)
    {
        dim3 grid(CDIM / 128, TOKG / 128);
        hgemm_kernel<<<grid, 256, GSMEM>>>(p_attn, p_wprojT, b_proj, x,
                                           p_x2, nullptr,
                                           TOKG, CDIM, CDIM, 2);
    }

    // 5) LN2 -> g_xn2 (half)
    ln_kernel<<<TOKG / 8, 256>>>(p_x2, p_xn2, g2, b2);

    // 6) FC1 + GELU -> g_hid (half)
    {
        dim3 grid(MLPD / 128, TOKG / 128);
        hgemm_kernel<<<grid, 256, GSMEM>>>(p_xn2, p_w1T, b1m, nullptr,
                                           nullptr, p_hid,
                                           TOKG, MLPD, CDIM, 1);
    }

    // 7) FC2 + residual(g_x2) -> out (float)
    {
        dim3 grid(CDIM / 128, TOKG / 128);
        hgemm_kernel<<<grid, 256, GSMEM>>>(p_hid, p_w2T, b2m, p_x2,
                                           out, nullptr,
                                           TOKG, CDIM, MLPD, 2);
    }
}

// round 16
// speedup vs baseline: 1.6016x; 1.0367x over previous
#include <cuda_runtime.h>
#include <cuda_fp16.h>
#include <math.h>
#include <stdint.h>

// ---------------- problem constants ----------------
#define BATCH   2
#define HT      64
#define WT      64
#define CDIM    768
#define WIN     14
#define NWIN1   5
#define NWINB   25
#define NW      50
#define HW      196
#define NHEAD   12
#define HD      64
#define MLPD    3072
#define TOKG    (BATCH*HT*WT)  // 8192 global tokens
#define EPS     1e-5f

// ---------------- scratch (global token layout everywhere) ----------------
__device__ __half g_xn1 [TOKG * CDIM];
__device__ __half g_qkv [TOKG * 3 * CDIM];
__device__ __half g_attn[TOKG * CDIM];
__device__ float  g_x2  [TOKG * CDIM];
__device__ __half g_xn2 [TOKG * CDIM];
__device__ __half g_hid [TOKG * MLPD];
__device__ __half g_wqkvT[3 * CDIM * CDIM];
__device__ __half g_wprojT[CDIM * CDIM];
__device__ __half g_w1T  [MLPD * CDIM];
__device__ __half g_w2T  [CDIM * MLPD];

// ---------------- helpers ----------------
__device__ __forceinline__ void win_map(int row, int& gidx, bool& valid) {
    int n  = row / HW, t = row % HW;
    int bb = n / NWINB, nw = n % NWINB;
    int wh = nw / NWIN1, ww = nw % NWIN1;
    int ii = t / WIN,    jj = t % WIN;
    int gh = wh * WIN + ii, gw = ww * WIN + jj;
    valid = (gh < HT) && (gw < WT);
    gidx  = (bb * HT + gh) * WT + gw;
}
__device__ __forceinline__ uint32_t smem_u32(const void* p) {
    return (uint32_t)__cvta_generic_to_shared(p);
}
__device__ __forceinline__ void cp16(uint32_t dst, const void* src) {
    asm volatile("cp.async.cg.shared.global [%0], [%1], 16;\n"
                 :: "r"(dst), "l"(src));
}
__device__ __forceinline__ void ldsm4(uint32_t& r0, uint32_t& r1,
                                      uint32_t& r2, uint32_t& r3, uint32_t a) {
    asm volatile("ldmatrix.sync.aligned.m8n8.x4.shared.b16 {%0,%1,%2,%3}, [%4];"
                 : "=r"(r0), "=r"(r1), "=r"(r2), "=r"(r3) : "r"(a));
}
__device__ __forceinline__ void mma16816(float* c, const uint32_t* a,
                                         const uint32_t* b) {
    asm volatile(
        "mma.sync.aligned.m16n8k16.row.col.f32.f16.f16.f32 "
        "{%0,%1,%2,%3}, {%4,%5,%6,%7}, {%8,%9}, {%0,%1,%2,%3};\n"
        : "+f"(c[0]), "+f"(c[1]), "+f"(c[2]), "+f"(c[3])
        : "r"(a[0]), "r"(a[1]), "r"(a[2]), "r"(a[3]),
          "r"(b[0]), "r"(b[1]));
}
__device__ __forceinline__ void barpair(int id) {
    asm volatile("bar.sync %0, 64;" :: "r"(id) : "memory");
}

// ---------------- merged weight transpose + fp32->fp16 (one launch) ---------
__global__ __launch_bounds__(256) void f2hT_all_kernel(
    const float* __restrict__ w_qkv, const float* __restrict__ w_proj,
    const float* __restrict__ w1,    const float* __restrict__ w2)
{
    __shared__ float t[32][33];
    int tile = blockIdx.x;
    const float* src; __half* dst; int K, N, bx, by;
    if (tile < 1728)      { src = w_qkv;  dst = g_wqkvT;  K = CDIM; N = 3*CDIM;
                            bx = tile % 72; by = tile / 72; }
    else if (tile < 2304) { tile -= 1728; src = w_proj; dst = g_wprojT;
                            K = CDIM; N = CDIM; bx = tile % 24; by = tile / 24; }
    else if (tile < 4608) { tile -= 2304; src = w1; dst = g_w1T;
                            K = CDIM; N = MLPD; bx = tile % 96; by = tile / 96; }
    else                  { tile -= 4608; src = w2; dst = g_w2T;
                            K = MLPD; N = CDIM; bx = tile % 24; by = tile / 24; }
    int n0 = bx * 32, k0 = by * 32;
    int tx = threadIdx.x, ty = threadIdx.y;
    #pragma unroll
    for (int i = 0; i < 32; i += 8)
        t[ty + i][tx] = src[(size_t)(k0 + ty + i) * N + n0 + tx];
    __syncthreads();
    #pragma unroll
    for (int i = 0; i < 32; i += 8)
        dst[(size_t)(n0 + ty + i) * K + k0 + tx] = __float2half_rn(t[tx][ty + i]);
}

// ---------------- LayerNorm: warp-per-row ----------------
__global__ __launch_bounds__(256) void ln_kernel(
    const float* __restrict__ in, __half* __restrict__ outp,
    const float* __restrict__ g, const float* __restrict__ b)
{
    int warp = threadIdx.x >> 5, lane = threadIdx.x & 31;
    int row  = blockIdx.x * 8 + warp;
    const float* xr = in + (size_t)row * CDIM;
    __half* orow = outp + (size_t)row * CDIM;

    float4 v[6];
    float s = 0.f, sq = 0.f;
    #pragma unroll
    for (int j = 0; j < 6; j++) {
        v[j] = *(const float4*)&xr[j * 128 + lane * 4];
        s  += v[j].x + v[j].y + v[j].z + v[j].w;
        sq += v[j].x * v[j].x + v[j].y * v[j].y
            + v[j].z * v[j].z + v[j].w * v[j].w;
    }
    #pragma unroll
    for (int off = 16; off; off >>= 1) {
        s  += __shfl_xor_sync(~0u, s,  off);
        sq += __shfl_xor_sync(~0u, sq, off);
    }
    float mean = s * (1.f / CDIM);
    float var  = sq * (1.f / CDIM) - mean * mean;
    float rstd = rsqrtf(var + EPS);
    #pragma unroll
    for (int j = 0; j < 6; j++) {
        int c = j * 128 + lane * 4;
        float4 g4 = *(const float4*)&g[c];
        float4 b4 = *(const float4*)&b[c];
        __half2 h0 = __floats2half2_rn((v[j].x - mean) * rstd * g4.x + b4.x,
                                       (v[j].y - mean) * rstd * g4.y + b4.y);
        __half2 h1 = __floats2half2_rn((v[j].z - mean) * rstd * g4.z + b4.z,
                                       (v[j].w - mean) * rstd * g4.w + b4.w);
        *(__half2*)&orow[c]     = h0;
        *(__half2*)&orow[c + 2] = h1;
    }
}

// ---------------- FP16 GEMM: KTILE=32, 3-stage cp.async (winner config) -----
#define KTILE 32
#define AST   40
#define STG_H (128 * AST)
#define STG_B (STG_H * 2)
#define GSMEM (6 * STG_B)

__global__ __launch_bounds__(256, 2) void hgemm_kernel(
    const __half* __restrict__ A, const __half* __restrict__ Bt,
    const float* __restrict__ bias, const float* __restrict__ res,
    float* __restrict__ Cf, __half* __restrict__ Ch,
    int M, int N, int K, int mode)
{
    extern __shared__ __half shh[];
    __half* AsS = shh;
    __half* BsS = shh + 3 * STG_H;

    int tid  = threadIdx.x;
    int warp = tid >> 5, lane = tid & 31;
    int wm = warp >> 2, wn = warp & 3;
    int gq = lane >> 2, tr = lane & 3;
    int bm = blockIdx.y * 128, bn = blockIdx.x * 128;

    int srow = tid >> 1;
    int scol = (tid & 1) * 16;
    const __half* Ag = A  + (size_t)(bm + srow) * K + scol;
    const __half* Bg = Bt + (size_t)(bn + srow) * K + scol;
    uint32_t as_st = smem_u32(AsS + srow * AST + scol);
    uint32_t bs_st = smem_u32(BsS + srow * AST + scol);

    uint32_t as_base = smem_u32(AsS);
    uint32_t bs_base = smem_u32(BsS);
    int fr = lane & 15;
    int fc = (lane >> 4) * 8;

    float acc[4][4][4];
    #pragma unroll
    for (int mi = 0; mi < 4; mi++)
        #pragma unroll
        for (int ni = 0; ni < 4; ni++)
            #pragma unroll
            for (int r = 0; r < 4; r++) acc[mi][ni][r] = 0.f;

    int T = K / KTILE;

    #define FILL(t, s) do {                                        \
        const __half* ag_ = Ag + (t) * KTILE;                      \
        uint32_t ad_ = as_st + (s) * STG_B;                        \
        cp16(ad_,      ag_);                                       \
        cp16(ad_ + 16, ag_ + 8);                                   \
        const __half* bg_ = Bg + (t) * KTILE;                      \
        uint32_t bd_ = bs_st + (s) * STG_B;                        \
        cp16(bd_,      bg_);                                       \
        cp16(bd_ + 16, bg_ + 8);                                   \
        asm volatile("cp.async.commit_group;\n");                  \
    } while (0)

    FILL(0, 0);
    FILL(1, 1);

    int s = 0;
    for (int t = 0; t < T; t++) {
        if (t + 1 < T) asm volatile("cp.async.wait_group 1;\n");
        else           asm volatile("cp.async.wait_group 0;\n");
        __syncthreads();
        if (t + 2 < T) {
            int sf = (s == 0) ? 2 : s - 1;
            FILL(t + 2, sf);
        }

        uint32_t ab = as_base + s * STG_B;
        uint32_t bb = bs_base + s * STG_B;
        #pragma unroll
        for (int kk = 0; kk < KTILE; kk += 16) {
            uint32_t af[4][4], bf[4][2];
            #pragma unroll
            for (int mi = 0; mi < 4; mi++) {
                uint32_t addr = ab +
                    (((wm * 64 + mi * 16 + fr) * AST) + kk + fc) * 2;
                ldsm4(af[mi][0], af[mi][1], af[mi][2], af[mi][3], addr);
            }
            #pragma unroll
            for (int nh = 0; nh < 2; nh++) {
                uint32_t addr = bb +
                    (((wn * 32 + nh * 16 + fr) * AST) + kk + fc) * 2;
                ldsm4(bf[2 * nh][0], bf[2 * nh + 1][0],
                      bf[2 * nh][1], bf[2 * nh + 1][1], addr);
            }
            #pragma unroll
            for (int mi = 0; mi < 4; mi++)
                #pragma unroll
                for (int ni = 0; ni < 4; ni++)
                    mma16816(acc[mi][ni], af[mi], bf[ni]);
        }
        s = (s == 2) ? 0 : s + 1;
    }
    #undef FILL

    #pragma unroll
    for (int mi = 0; mi < 4; mi++) {
        int rbase = bm + wm * 64 + mi * 16 + gq;
        #pragma unroll
        for (int h = 0; h < 2; h++) {
            int row = rbase + 8 * h;
            #pragma unroll
            for (int ni = 0; ni < 4; ni++) {
                int col = bn + wn * 32 + ni * 8 + tr * 2;
                float v0 = acc[mi][ni][2 * h]     + bias[col];
                float v1 = acc[mi][ni][2 * h + 1] + bias[col + 1];
                if (mode == 0) {
                    *(__half2*)&Ch[(size_t)row * N + col] =
                        __floats2half2_rn(v0, v1);
                } else if (mode == 1) {
                    v0 = 0.5f * v0 * (1.f + erff(v0 * 0.70710678118654752f));
                    v1 = 0.5f * v1 * (1.f + erff(v1 * 0.70710678118654752f));
                    *(__half2*)&Ch[(size_t)row * N + col] =
                        __floats2half2_rn(v0, v1);
                } else {
                    Cf[(size_t)row * N + col]     = v0 + res[(size_t)row * N + col];
                    Cf[(size_t)row * N + col + 1] = v1 + res[(size_t)row * N + col + 1];
                }
            }
        }
    }
}

// ---------------- tensor-core window attention ------------------------------
// Register softmax; no S buffer; pair-scoped named barriers.
#define QKS   72
#define VPS   216
#define BFS   34
#define F_RED 0                          // redA[4][16][2], redB[4][16][2]
#define F_BH  256
#define F_BW  (F_BH + HW * BFS)
#define F_GT  (F_BW + HW * BFS)
#define F_TOT (F_GT + HW)
#define H_Q   0
#define H_K   (HW * QKS)
#define H_VT  (H_K + HW * QKS)
#define H_P   (H_VT + HD * VPS)
#define H_RH  (H_P + 64 * VPS)
#define H_RW  (H_RH + 32 * QKS)
#define H_TOT (H_RW + 32 * QKS)
#define ATTN_SMEM_BYTES (F_TOT * 4 + H_TOT * 2)

__global__ __launch_bounds__(256, 1) void attn_kernel(
    const float* __restrict__ rel_h, const float* __restrict__ rel_w,
    const float* __restrict__ b_qkv)
{
    extern __shared__ float smf[];
    float* redA = smf + F_RED;        // [4][16][2]
    float* redB = redA + 128;         // [4][16][2]
    float* bhf  = smf + F_BH;
    float* bwf  = smf + F_BW;
    int*   gtab = (int*)(smf + F_GT);
    __half* hbase = (__half*)(smf + F_TOT);
    __half* qs  = hbase + H_Q;
    __half* kss = hbase + H_K;
    __half* vts = hbase + H_VT;
    __half* ps  = hbase + H_P;
    __half* rhh = hbase + H_RH;
    __half* rwh = hbase + H_RW;

    int w0   = blockIdx.x;
    int head = blockIdx.y;
    int tid  = threadIdx.x;
    int warp = tid >> 5, lane = tid & 31;
    int gq = lane >> 2, tr = lane & 3;
    int fr = lane & 15;
    int fc = (lane >> 4) * 8;

    uint32_t qs_b = smem_u32(qs);
    uint32_t ks_b = smem_u32(kss);
    uint32_t vt_b = smem_u32(vts);
    uint32_t ps_b = smem_u32(ps);
    uint32_t rh_b = smem_u32(rhh);
    uint32_t rw_b = smem_u32(rwh);

    if (tid < HW) {
        int gi; bool v;
        win_map(w0 * HW + tid, gi, v);
        gtab[tid] = v ? gi : -1;
    }
    for (int idx = tid; idx < 32 * 16; idx += 256) {
        int rrow = idx >> 4, d4 = (idx & 15) * 4;
        if (rrow < 27) {
            float4 fh = *(const float4*)&rel_h[rrow * HD + d4];
            float4 fw = *(const float4*)&rel_w[rrow * HD + d4];
            *(__half2*)&rhh[rrow * QKS + d4]     = __floats2half2_rn(fh.x, fh.y);
            *(__half2*)&rhh[rrow * QKS + d4 + 2] = __floats2half2_rn(fh.z, fh.w);
            *(__half2*)&rwh[rrow * QKS + d4]     = __floats2half2_rn(fw.x, fw.y);
            *(__half2*)&rwh[rrow * QKS + d4 + 2] = __floats2half2_rn(fw.z, fw.w);
        } else {
            __half2 z = __floats2half2_rn(0.f, 0.f);
            *(__half2*)&rhh[rrow * QKS + d4]     = z;
            *(__half2*)&rhh[rrow * QKS + d4 + 2] = z;
            *(__half2*)&rwh[rrow * QKS + d4]     = z;
            *(__half2*)&rwh[rrow * QKS + d4 + 2] = z;
        }
    }
    __syncthreads();

    // ---- stage Q,K (row-major) and V (transposed), vectorized ----
    const float* bq = b_qkv + head * HD;
    for (int idx = tid; idx < HW * 16; idx += 256) {
        int row = idx >> 4, d = (idx & 15) * 4;
        int gi = gtab[row];
        __half vtmp[4];
        if (gi >= 0) {
            const __half* src = g_qkv + (size_t)gi * (3 * CDIM) + head * HD + d;
            *(uint2*)&qs [row * QKS + d] = *(const uint2*)(src);
            *(uint2*)&kss[row * QKS + d] = *(const uint2*)(src + CDIM);
            *(uint2*)vtmp = *(const uint2*)(src + 2 * CDIM);
        } else {
            #pragma unroll
            for (int j = 0; j < 4; j++) {
                qs [row * QKS + d + j] = __float2half_rn(bq[d + j]);
                kss[row * QKS + d + j] = __float2half_rn(bq[CDIM + d + j]);
                vtmp[j] = __float2half_rn(bq[2 * CDIM + d + j]);
            }
        }
        #pragma unroll
        for (int j = 0; j < 4; j++)
            vts[(d + j) * VPS + row] = vtmp[j];
    }
    for (int idx = tid; idx < HD * 12; idx += 256) {
        int d = idx / 12;
        vts[d * VPS + HW + idx % 12] = __float2half_rn(0.f);
    }
    __syncthreads();

    // ---- bias tables via MMA: bhf[196][27] = Q*RhT, bwf = Q*RwT ----
    for (int st = warp; st < 13; st += 8) {
        float ba[4][4], bb2[4][4];
        #pragma unroll
        for (int g = 0; g < 4; g++)
            #pragma unroll
            for (int r = 0; r < 4; r++) { ba[g][r] = 0.f; bb2[g][r] = 0.f; }
        int mrow = st * 16;
        #pragma unroll
        for (int kk = 0; kk < HD; kk += 16) {
            uint32_t qf[4];
            int ar = mrow + fr; if (ar > HW - 1) ar = HW - 1;
            ldsm4(qf[0], qf[1], qf[2], qf[3], qs_b + (ar * QKS + kk + fc) * 2);
            #pragma unroll
            for (int g = 0; g < 2; g++) {
                uint32_t hf0[2], hf1[2], wf0[2], wf1[2];
                ldsm4(hf0[0], hf1[0], hf0[1], hf1[1],
                      rh_b + ((g * 16 + fr) * QKS + kk + fc) * 2);
                ldsm4(wf0[0], wf1[0], wf0[1], wf1[1],
                      rw_b + ((g * 16 + fr) * QKS + kk + fc) * 2);
                mma16816(ba[2 * g],      qf, hf0);
                mma16816(ba[2 * g + 1],  qf, hf1);
                mma16816(bb2[2 * g],     qf, wf0);
                mma16816(bb2[2 * g + 1], qf, wf1);
            }
        }
        #pragma unroll
        for (int g = 0; g < 4; g++) {
            int col = g * 8 + tr * 2;
            int r0 = mrow + gq;
            if (r0 < HW) {
                *(float2*)&bhf[r0 * BFS + col] = make_float2(ba[g][0], ba[g][1]);
                *(float2*)&bwf[r0 * BFS + col] = make_float2(bb2[g][0], bb2[g][1]);
            }
            if (r0 + 8 < HW) {
                *(float2*)&bhf[(r0 + 8) * BFS + col] = make_float2(ba[g][2], ba[g][3]);
                *(float2*)&bwf[(r0 + 8) * BFS + col] = make_float2(bb2[g][2], bb2[g][3]);
            }
        }
    }
    __syncthreads();

    int stripe = warp >> 1, nh = warp & 1;
    int ngr   = nh ? 6 : 7;
    int nbase = nh ? 112 : 0;
    int barid = 1 + stripe;

    for (int c = 0; c < 4; c++) {
        int q0 = c * 64;
        int rows = (HW - q0 < 64) ? (HW - q0) : 64;
        int nstripes = (rows + 15) >> 4;

        if (stripe < nstripes) {
            int mrow = q0 + stripe * 16;
            float sacc[7][2][4];
            #pragma unroll
            for (int g = 0; g < 7; g++)
                #pragma unroll
                for (int u = 0; u < 2; u++)
                    #pragma unroll
                    for (int r = 0; r < 4; r++) sacc[g][u][r] = 0.f;

            // ---- QK^T MMA ----
            #pragma unroll
            for (int kk = 0; kk < HD; kk += 16) {
                uint32_t af[4];
                int ar = mrow + fr; if (ar > HW - 1) ar = HW - 1;
                ldsm4(af[0], af[1], af[2], af[3],
                      qs_b + (ar * QKS + kk + fc) * 2);
                #pragma unroll
                for (int g = 0; g < 7; g++) {
                    if (g < ngr) {
                        int br = nbase + g * 16 + fr; if (br > HW - 1) br = HW - 1;
                        uint32_t bf0[2], bf1[2];
                        ldsm4(bf0[0], bf1[0], bf0[1], bf1[1],
                              ks_b + (br * QKS + kk + fc) * 2);
                        mma16816(sacc[g][0], af, bf0);
                        mma16816(sacc[g][1], af, bf1);
                    }
                }
            }

            // ---- register softmax ----
            int qa = mrow + gq, qb = qa + 8;
            int qca = qa < HW ? qa : HW - 1;
            int qcb = qb < HW ? qb : HW - 1;
            int hqa = qca / WIN, wqa = qca % WIN;
            int hqb = qcb / WIN, wqb = qcb % WIN;
            const float* bha = &bhf[qca * BFS + (WIN - 1)];
            const float* bwa = &bwf[qca * BFS + (WIN - 1)];
            const float* bhb = &bhf[qcb * BFS + (WIN - 1)];
            const float* bwb = &bwf[qcb * BFS + (WIN - 1)];

            float mx0 = -1e30f, mx1 = -1e30f;
            #pragma unroll
            for (int g = 0; g < 7; g++) {
                if (g < ngr) {
                    #pragma unroll
                    for (int u = 0; u < 2; u++) {
                        int col0 = nbase + g * 16 + u * 8 + tr * 2;
                        #pragma unroll
                        for (int cc = 0; cc < 2; cc++) {
                            int col = col0 + cc;
                            int kh = col / WIN, kw = col % WIN;
                            bool valid = col < HW;
                            float t0 = valid
                                ? sacc[g][u][cc] * 0.125f + bha[hqa - kh] + bwa[wqa - kw]
                                : -1e30f;
                            float t1 = valid
                                ? sacc[g][u][2 + cc] * 0.125f + bhb[hqb - kh] + bwb[wqb - kw]
                                : -1e30f;
                            sacc[g][u][cc]     = t0;
                            sacc[g][u][2 + cc] = t1;
                            mx0 = fmaxf(mx0, t0);
                            mx1 = fmaxf(mx1, t1);
                        }
                    }
                }
            }
            mx0 = fmaxf(mx0, __shfl_xor_sync(~0u, mx0, 1));
            mx0 = fmaxf(mx0, __shfl_xor_sync(~0u, mx0, 2));
            mx1 = fmaxf(mx1, __shfl_xor_sync(~0u, mx1, 1));
            mx1 = fmaxf(mx1, __shfl_xor_sync(~0u, mx1, 2));
            if (tr == 0) {
                redA[(stripe * 16 + gq) * 2 + nh]     = mx0;
                redA[(stripe * 16 + gq + 8) * 2 + nh] = mx1;
            }
            barpair(barid);
            mx0 = fmaxf(mx0, redA[(stripe * 16 + gq) * 2 + (nh ^ 1)]);
            mx1 = fmaxf(mx1, redA[(stripe * 16 + gq + 8) * 2 + (nh ^ 1)]);

            float s0 = 0.f, s1 = 0.f;
            #pragma unroll
            for (int g = 0; g < 7; g++) {
                if (g < ngr) {
                    #pragma unroll
                    for (int u = 0; u < 2; u++) {
                        #pragma unroll
                        for (int cc = 0; cc < 2; cc++) {
                            float e0 = __expf(sacc[g][u][cc]     - mx0);
                            float e1 = __expf(sacc[g][u][2 + cc] - mx1);
                            sacc[g][u][cc]     = e0;
                            sacc[g][u][2 + cc] = e1;
                            s0 += e0; s1 += e1;
                        }
                    }
                }
            }
            s0 += __shfl_xor_sync(~0u, s0, 1);
            s0 += __shfl_xor_sync(~0u, s0, 2);
            s1 += __shfl_xor_sync(~0u, s1, 1);
            s1 += __shfl_xor_sync(~0u, s1, 2);
            if (tr == 0) {
                redB[(stripe * 16 + gq) * 2 + nh]     = s0;
                redB[(stripe * 16 + gq + 8) * 2 + nh] = s1;
            }
            barpair(barid);
            s0 += redB[(stripe * 16 + gq) * 2 + (nh ^ 1)];
            s1 += redB[(stripe * 16 + gq + 8) * 2 + (nh ^ 1)];
            float inv0 = 1.f / s0, inv1 = 1.f / s1;

            int lr0 = stripe * 16 + gq;
            #pragma unroll
            for (int g = 0; g < 7; g++) {
                if (g < ngr) {
                    #pragma unroll
                    for (int u = 0; u < 2; u++) {
                        int col0 = nbase + g * 16 + u * 8 + tr * 2;
                        *(__half2*)&ps[lr0 * VPS + col0] =
                            __floats2half2_rn(sacc[g][u][0] * inv0,
                                              sacc[g][u][1] * inv0);
                        *(__half2*)&ps[(lr0 + 8) * VPS + col0] =
                            __floats2half2_rn(sacc[g][u][2] * inv1,
                                              sacc[g][u][3] * inv1);
                    }
                }
            }
            barpair(barid);   // partner's P rows complete before PV reads

            // ---- PV ----
            int d0b = nh * 32;
            float oacc[4][4];
            #pragma unroll
            for (int ni = 0; ni < 4; ni++)
                #pragma unroll
                for (int r = 0; r < 4; r++) oacc[ni][r] = 0.f;

            #pragma unroll
            for (int kk = 0; kk < 208; kk += 16) {
                uint32_t af[4];
                ldsm4(af[0], af[1], af[2], af[3],
                      ps_b + ((stripe * 16 + fr) * VPS + kk + fc) * 2);
                #pragma unroll
                for (int g = 0; g < 2; g++) {
                    uint32_t bf0[2], bf1[2];
                    ldsm4(bf0[0], bf1[0], bf0[1], bf1[1],
                          vt_b + ((d0b + g * 16 + fr) * VPS + kk + fc) * 2);
                    mma16816(oacc[2 * g],     af, bf0);
                    mma16816(oacc[2 * g + 1], af, bf1);
                }
            }
            #pragma unroll
            for (int ni = 0; ni < 4; ni++) {
                int col = head * HD + d0b + ni * 8 + tr * 2;
                #pragma unroll
                for (int h = 0; h < 2; h++) {
                    int grow = q0 + stripe * 16 + gq + 8 * h;
                    if (grow < HW) {
                        int gi = gtab[grow];
                        if (gi >= 0) {
                            __half* op = g_attn + (size_t)gi * CDIM + col;
                            *(__half2*)op = __floats2half2_rn(oacc[ni][2 * h],
                                                              oacc[ni][2 * h + 1]);
                        }
                    }
                }
            }
        }
    }
}

// ---------------- launcher ----------------
extern "C" void kernel_launch(void* const* d_in, const int* in_sizes, int n_in,
                              void* d_out, int out_size)
{
    const float* x      = (const float*)d_in[0];
    const float* g1     = (const float*)d_in[1];
    const float* b1     = (const float*)d_in[2];
    const float* w_qkv  = (const float*)d_in[3];
    const float* b_qkv  = (const float*)d_in[4];
    const float* w_proj = (const float*)d_in[5];
    const float* b_proj = (const float*)d_in[6];
    const float* rel_h  = (const float*)d_in[7];
    const float* rel_w  = (const float*)d_in[8];
    const float* g2     = (const float*)d_in[9];
    const float* b2     = (const float*)d_in[10];
    const float* w1     = (const float*)d_in[11];
    const float* b1m    = (const float*)d_in[12];
    const float* w2     = (const float*)d_in[13];
    const float* b2m    = (const float*)d_in[14];
    float* out = (float*)d_out;

    __half *p_xn1, *p_qkv, *p_attn, *p_xn2, *p_hid;
    __half *p_wqkvT, *p_wprojT, *p_w1T, *p_w2T;
    float *p_x2;
    cudaGetSymbolAddress((void**)&p_xn1,   g_xn1);
    cudaGetSymbolAddress((void**)&p_qkv,   g_qkv);
    cudaGetSymbolAddress((void**)&p_attn,  g_attn);
    cudaGetSymbolAddress((void**)&p_x2,    g_x2);
    cudaGetSymbolAddress((void**)&p_xn2,   g_xn2);
    cudaGetSymbolAddress((void**)&p_hid,   g_hid);
    cudaGetSymbolAddress((void**)&p_wqkvT, g_wqkvT);
    cudaGetSymbolAddress((void**)&p_wprojT,g_wprojT);
    cudaGetSymbolAddress((void**)&p_w1T,   g_w1T);
    cudaGetSymbolAddress((void**)&p_w2T,   g_w2T);

    static int attr_set = 0;
    if (!attr_set) {
        cudaFuncSetAttribute(attn_kernel,
            cudaFuncAttributeMaxDynamicSharedMemorySize, ATTN_SMEM_BYTES);
        cudaFuncSetAttribute(hgemm_kernel,
            cudaFuncAttributeMaxDynamicSharedMemorySize, GSMEM);
        attr_set = 1;
    }

    // 0) all weight transposes in one launch
    f2hT_all_kernel<<<6912, dim3(32, 8)>>>(w_qkv, w_proj, w1, w2);

    // 1) LN1 -> g_xn1 (half)
    ln_kernel<<<TOKG / 8, 256>>>(x, p_xn1, g1, b1);

    // 2) QKV GEMM -> g_qkv (half)
    {
        dim3 grid((3 * CDIM) / 128, TOKG / 128);
        hgemm_kernel<<<grid, 256, GSMEM>>>(p_xn1, p_wqkvT, b_qkv, nullptr,
                                           nullptr, p_qkv,
                                           TOKG, 3 * CDIM, CDIM, 0);
    }

    // 3) tensor-core attention -> g_attn (half)
    attn_kernel<<<dim3(NW, NHEAD), 256, ATTN_SMEM_BYTES>>>(rel_h, rel_w, b_qkv);

    // 4) proj GEMM + residual(x) -> g_x2 (float)
    {
        dim3 grid(CDIM / 128, TOKG / 128);
        hgemm_kernel<<<grid, 256, GSMEM>>>(p_attn, p_wprojT, b_proj, x,
                                           p_x2, nullptr,
                                           TOKG, CDIM, CDIM, 2);
    }

    // 5) LN2 -> g_xn2 (half)
    ln_kernel<<<TOKG / 8, 256>>>(p_x2, p_xn2, g2, b2);

    // 6) FC1 + GELU -> g_hid (half)
    {
        dim3 grid(MLPD / 128, TOKG / 128);
        hgemm_kernel<<<grid, 256, GSMEM>>>(p_xn2, p_w1T, b1m, nullptr,
                                           nullptr, p_hid,
                                           TOKG, MLPD, CDIM, 1);
    }

    // 7) FC2 + residual(g_x2) -> out (float)
    {
        dim3 grid(CDIM / 128, TOKG / 128);
        hgemm_kernel<<<grid, 256, GSMEM>>>(p_hid, p_w2T, b2m, p_x2,
                                           out, nullptr,
                                           TOKG, CDIM, MLPD, 2);
    }
}

// round 17
// speedup vs baseline: 1.6440x; 1.0265x over previous
#include <cuda_runtime.h>
#include <cuda_fp16.h>
#include <math.h>
#include <stdint.h>

// ---------------- problem constants ----------------
#define BATCH   2
#define HT      64
#define WT      64
#define CDIM    768
#define WIN     14
#define NWIN1   5
#define NWINB   25
#define NW      50
#define HW      196
#define NHEAD   12
#define HD      64
#define MLPD    3072
#define TOKG    (BATCH*HT*WT)  // 8192 global tokens
#define EPS     1e-5f

// ---------------- scratch (global token layout everywhere) ----------------
__device__ __half g_xn1 [TOKG * CDIM];
__device__ __half g_qkv [TOKG * 3 * CDIM];
__device__ __half g_attn[TOKG * CDIM];
__device__ float  g_x2  [TOKG * CDIM];
__device__ __half g_xn2 [TOKG * CDIM];
__device__ __half g_hid [TOKG * MLPD];
__device__ __half g_wqkvT[3 * CDIM * CDIM];
__device__ __half g_wprojT[CDIM * CDIM];
__device__ __half g_w1T  [MLPD * CDIM];
__device__ __half g_w2T  [CDIM * MLPD];

// ---------------- helpers ----------------
__device__ __forceinline__ void win_map(int row, int& gidx, bool& valid) {
    int n  = row / HW, t = row % HW;
    int bb = n / NWINB, nw = n % NWINB;
    int wh = nw / NWIN1, ww = nw % NWIN1;
    int ii = t / WIN,    jj = t % WIN;
    int gh = wh * WIN + ii, gw = ww * WIN + jj;
    valid = (gh < HT) && (gw < WT);
    gidx  = (bb * HT + gh) * WT + gw;
}
__device__ __forceinline__ uint32_t smem_u32(const void* p) {
    return (uint32_t)__cvta_generic_to_shared(p);
}
__device__ __forceinline__ void cp16(uint32_t dst, const void* src) {
    asm volatile("cp.async.cg.shared.global [%0], [%1], 16;\n"
                 :: "r"(dst), "l"(src));
}
__device__ __forceinline__ void ldsm4(uint32_t& r0, uint32_t& r1,
                                      uint32_t& r2, uint32_t& r3, uint32_t a) {
    asm volatile("ldmatrix.sync.aligned.m8n8.x4.shared.b16 {%0,%1,%2,%3}, [%4];"
                 : "=r"(r0), "=r"(r1), "=r"(r2), "=r"(r3) : "r"(a));
}
__device__ __forceinline__ void ldsm4t(uint32_t& r0, uint32_t& r1,
                                       uint32_t& r2, uint32_t& r3, uint32_t a) {
    asm volatile("ldmatrix.sync.aligned.m8n8.x4.trans.shared.b16 {%0,%1,%2,%3}, [%4];"
                 : "=r"(r0), "=r"(r1), "=r"(r2), "=r"(r3) : "r"(a));
}
__device__ __forceinline__ void mma16816(float* c, const uint32_t* a,
                                         const uint32_t* b) {
    asm volatile(
        "mma.sync.aligned.m16n8k16.row.col.f32.f16.f16.f32 "
        "{%0,%1,%2,%3}, {%4,%5,%6,%7}, {%8,%9}, {%0,%1,%2,%3};\n"
        : "+f"(c[0]), "+f"(c[1]), "+f"(c[2]), "+f"(c[3])
        : "r"(a[0]), "r"(a[1]), "r"(a[2]), "r"(a[3]),
          "r"(b[0]), "r"(b[1]));
}
__device__ __forceinline__ void barpair(int id) {
    asm volatile("bar.sync %0, 64;" :: "r"(id) : "memory");
}

// ---------------- merged weight transpose + fp32->fp16 (one launch) ---------
__global__ __launch_bounds__(256) void f2hT_all_kernel(
    const float* __restrict__ w_qkv, const float* __restrict__ w_proj,
    const float* __restrict__ w1,    const float* __restrict__ w2)
{
    __shared__ float t[32][33];
    int tile = blockIdx.x;
    const float* src; __half* dst; int K, N, bx, by;
    if (tile < 1728)      { src = w_qkv;  dst = g_wqkvT;  K = CDIM; N = 3*CDIM;
                            bx = tile % 72; by = tile / 72; }
    else if (tile < 2304) { tile -= 1728; src = w_proj; dst = g_wprojT;
                            K = CDIM; N = CDIM; bx = tile % 24; by = tile / 24; }
    else if (tile < 4608) { tile -= 2304; src = w1; dst = g_w1T;
                            K = CDIM; N = MLPD; bx = tile % 96; by = tile / 96; }
    else                  { tile -= 4608; src = w2; dst = g_w2T;
                            K = MLPD; N = CDIM; bx = tile % 24; by = tile / 24; }
    int n0 = bx * 32, k0 = by * 32;
    int tx = threadIdx.x, ty = threadIdx.y;
    #pragma unroll
    for (int i = 0; i < 32; i += 8)
        t[ty + i][tx] = src[(size_t)(k0 + ty + i) * N + n0 + tx];
    __syncthreads();
    #pragma unroll
    for (int i = 0; i < 32; i += 8)
        dst[(size_t)(n0 + ty + i) * K + k0 + tx] = __float2half_rn(t[tx][ty + i]);
}

// ---------------- LayerNorm: warp-per-row ----------------
__global__ __launch_bounds__(256) void ln_kernel(
    const float* __restrict__ in, __half* __restrict__ outp,
    const float* __restrict__ g, const float* __restrict__ b)
{
    int warp = threadIdx.x >> 5, lane = threadIdx.x & 31;
    int row  = blockIdx.x * 8 + warp;
    const float* xr = in + (size_t)row * CDIM;
    __half* orow = outp + (size_t)row * CDIM;

    float4 v[6];
    float s = 0.f, sq = 0.f;
    #pragma unroll
    for (int j = 0; j < 6; j++) {
        v[j] = *(const float4*)&xr[j * 128 + lane * 4];
        s  += v[j].x + v[j].y + v[j].z + v[j].w;
        sq += v[j].x * v[j].x + v[j].y * v[j].y
            + v[j].z * v[j].z + v[j].w * v[j].w;
    }
    #pragma unroll
    for (int off = 16; off; off >>= 1) {
        s  += __shfl_xor_sync(~0u, s,  off);
        sq += __shfl_xor_sync(~0u, sq, off);
    }
    float mean = s * (1.f / CDIM);
    float var  = sq * (1.f / CDIM) - mean * mean;
    float rstd = rsqrtf(var + EPS);
    #pragma unroll
    for (int j = 0; j < 6; j++) {
        int c = j * 128 + lane * 4;
        float4 g4 = *(const float4*)&g[c];
        float4 b4 = *(const float4*)&b[c];
        __half2 h0 = __floats2half2_rn((v[j].x - mean) * rstd * g4.x + b4.x,
                                       (v[j].y - mean) * rstd * g4.y + b4.y);
        __half2 h1 = __floats2half2_rn((v[j].z - mean) * rstd * g4.z + b4.z,
                                       (v[j].w - mean) * rstd * g4.w + b4.w);
        *(__half2*)&orow[c]     = h0;
        *(__half2*)&orow[c + 2] = h1;
    }
}

// ---------------- FP16 GEMM: KTILE=32, 3-stage cp.async (winner config) -----
#define KTILE 32
#define AST   40
#define STG_H (128 * AST)
#define STG_B (STG_H * 2)
#define GSMEM (6 * STG_B)

__global__ __launch_bounds__(256, 2) void hgemm_kernel(
    const __half* __restrict__ A, const __half* __restrict__ Bt,
    const float* __restrict__ bias, const float* __restrict__ res,
    float* __restrict__ Cf, __half* __restrict__ Ch,
    int M, int N, int K, int mode)
{
    extern __shared__ __half shh[];
    __half* AsS = shh;
    __half* BsS = shh + 3 * STG_H;

    int tid  = threadIdx.x;
    int warp = tid >> 5, lane = tid & 31;
    int wm = warp >> 2, wn = warp & 3;
    int gq = lane >> 2, tr = lane & 3;
    int bm = blockIdx.y * 128, bn = blockIdx.x * 128;

    int srow = tid >> 1;
    int scol = (tid & 1) * 16;
    const __half* Ag = A  + (size_t)(bm + srow) * K + scol;
    const __half* Bg = Bt + (size_t)(bn + srow) * K + scol;
    uint32_t as_st = smem_u32(AsS + srow * AST + scol);
    uint32_t bs_st = smem_u32(BsS + srow * AST + scol);

    uint32_t as_base = smem_u32(AsS);
    uint32_t bs_base = smem_u32(BsS);
    int fr = lane & 15;
    int fc = (lane >> 4) * 8;

    float acc[4][4][4];
    #pragma unroll
    for (int mi = 0; mi < 4; mi++)
        #pragma unroll
        for (int ni = 0; ni < 4; ni++)
            #pragma unroll
            for (int r = 0; r < 4; r++) acc[mi][ni][r] = 0.f;

    int T = K / KTILE;

    #define FILL(t, s) do {                                        \
        const __half* ag_ = Ag + (t) * KTILE;                      \
        uint32_t ad_ = as_st + (s) * STG_B;                        \
        cp16(ad_,      ag_);                                       \
        cp16(ad_ + 16, ag_ + 8);                                   \
        const __half* bg_ = Bg + (t) * KTILE;                      \
        uint32_t bd_ = bs_st + (s) * STG_B;                        \
        cp16(bd_,      bg_);                                       \
        cp16(bd_ + 16, bg_ + 8);                                   \
        asm volatile("cp.async.commit_group;\n");                  \
    } while (0)

    FILL(0, 0);
    FILL(1, 1);

    int s = 0;
    for (int t = 0; t < T; t++) {
        if (t + 1 < T) asm volatile("cp.async.wait_group 1;\n");
        else           asm volatile("cp.async.wait_group 0;\n");
        __syncthreads();
        if (t + 2 < T) {
            int sf = (s == 0) ? 2 : s - 1;
            FILL(t + 2, sf);
        }

        uint32_t ab = as_base + s * STG_B;
        uint32_t bb = bs_base + s * STG_B;
        #pragma unroll
        for (int kk = 0; kk < KTILE; kk += 16) {
            uint32_t af[4][4], bf[4][2];
            #pragma unroll
            for (int mi = 0; mi < 4; mi++) {
                uint32_t addr = ab +
                    (((wm * 64 + mi * 16 + fr) * AST) + kk + fc) * 2;
                ldsm4(af[mi][0], af[mi][1], af[mi][2], af[mi][3], addr);
            }
            #pragma unroll
            for (int nh = 0; nh < 2; nh++) {
                uint32_t addr = bb +
                    (((wn * 32 + nh * 16 + fr) * AST) + kk + fc) * 2;
                ldsm4(bf[2 * nh][0], bf[2 * nh + 1][0],
                      bf[2 * nh][1], bf[2 * nh + 1][1], addr);
            }
            #pragma unroll
            for (int mi = 0; mi < 4; mi++)
                #pragma unroll
                for (int ni = 0; ni < 4; ni++)
                    mma16816(acc[mi][ni], af[mi], bf[ni]);
        }
        s = (s == 2) ? 0 : s + 1;
    }
    #undef FILL

    #pragma unroll
    for (int mi = 0; mi < 4; mi++) {
        int rbase = bm + wm * 64 + mi * 16 + gq;
        #pragma unroll
        for (int h = 0; h < 2; h++) {
            int row = rbase + 8 * h;
            #pragma unroll
            for (int ni = 0; ni < 4; ni++) {
                int col = bn + wn * 32 + ni * 8 + tr * 2;
                float v0 = acc[mi][ni][2 * h]     + bias[col];
                float v1 = acc[mi][ni][2 * h + 1] + bias[col + 1];
                if (mode == 0) {
                    *(__half2*)&Ch[(size_t)row * N + col] =
                        __floats2half2_rn(v0, v1);
                } else if (mode == 1) {
                    v0 = 0.5f * v0 * (1.f + erff(v0 * 0.70710678118654752f));
                    v1 = 0.5f * v1 * (1.f + erff(v1 * 0.70710678118654752f));
                    *(__half2*)&Ch[(size_t)row * N + col] =
                        __floats2half2_rn(v0, v1);
                } else {
                    Cf[(size_t)row * N + col]     = v0 + res[(size_t)row * N + col];
                    Cf[(size_t)row * N + col + 1] = v1 + res[(size_t)row * N + col + 1];
                }
            }
        }
    }
}

// ---------------- tensor-core window attention ------------------------------
// Register softmax; V via ldmatrix.trans (no transpose staging); cp.async stage.
#define QKS   72
#define VPS   216
#define BFS   34
#define F_RED 0
#define F_BH  256
#define F_BW  (F_BH + HW * BFS)
#define F_GT  (F_BW + HW * BFS)
#define F_TOT (F_GT + HW)
#define H_Q   0
#define H_K   (HW * QKS)
#define H_V   (H_K + HW * QKS)          // V row-major [208][QKS]
#define H_P   (H_V + 208 * QKS)
#define H_RH  (H_P + 64 * VPS)
#define H_RW  (H_RH + 32 * QKS)
#define H_TOT (H_RW + 32 * QKS)
#define ATTN_SMEM_BYTES (F_TOT * 4 + H_TOT * 2)

__global__ __launch_bounds__(256, 1) void attn_kernel(
    const float* __restrict__ rel_h, const float* __restrict__ rel_w,
    const float* __restrict__ b_qkv)
{
    extern __shared__ float smf[];
    float* redA = smf + F_RED;
    float* redB = redA + 128;
    float* bhf  = smf + F_BH;
    float* bwf  = smf + F_BW;
    int*   gtab = (int*)(smf + F_GT);
    __half* hbase = (__half*)(smf + F_TOT);
    __half* qs  = hbase + H_Q;
    __half* kss = hbase + H_K;
    __half* vs  = hbase + H_V;
    __half* ps  = hbase + H_P;
    __half* rhh = hbase + H_RH;
    __half* rwh = hbase + H_RW;

    int w0   = blockIdx.x;
    int head = blockIdx.y;
    int tid  = threadIdx.x;
    int warp = tid >> 5, lane = tid & 31;
    int gq = lane >> 2, tr = lane & 3;
    int fr = lane & 15;
    int fc = (lane >> 4) * 8;

    uint32_t qs_b = smem_u32(qs);
    uint32_t ks_b = smem_u32(kss);
    uint32_t vs_b = smem_u32(vs);
    uint32_t ps_b = smem_u32(ps);
    uint32_t rh_b = smem_u32(rhh);
    uint32_t rw_b = smem_u32(rwh);

    if (tid < HW) {
        int gi; bool v;
        win_map(w0 * HW + tid, gi, v);
        gtab[tid] = v ? gi : -1;
    }
    for (int idx = tid; idx < 32 * 16; idx += 256) {
        int rrow = idx >> 4, d4 = (idx & 15) * 4;
        if (rrow < 27) {
            float4 fh = *(const float4*)&rel_h[rrow * HD + d4];
            float4 fw = *(const float4*)&rel_w[rrow * HD + d4];
            *(__half2*)&rhh[rrow * QKS + d4]     = __floats2half2_rn(fh.x, fh.y);
            *(__half2*)&rhh[rrow * QKS + d4 + 2] = __floats2half2_rn(fh.z, fh.w);
            *(__half2*)&rwh[rrow * QKS + d4]     = __floats2half2_rn(fw.x, fw.y);
            *(__half2*)&rwh[rrow * QKS + d4 + 2] = __floats2half2_rn(fw.z, fw.w);
        } else {
            __half2 z = __floats2half2_rn(0.f, 0.f);
            *(__half2*)&rhh[rrow * QKS + d4]     = z;
            *(__half2*)&rhh[rrow * QKS + d4 + 2] = z;
            *(__half2*)&rwh[rrow * QKS + d4]     = z;
            *(__half2*)&rwh[rrow * QKS + d4 + 2] = z;
        }
    }
    __syncthreads();

    // ---- stage Q,K,V row-major via cp.async (pad rows = bias constants) ----
    const float* bq = b_qkv + head * HD;
    for (int idx = tid; idx < HW * 8; idx += 256) {
        int row = idx >> 3, d8 = (idx & 7) * 8;
        int gi = gtab[row];
        if (gi >= 0) {
            const __half* src = g_qkv + (size_t)gi * (3 * CDIM) + head * HD + d8;
            cp16(smem_u32(&qs [row * QKS + d8]), src);
            cp16(smem_u32(&kss[row * QKS + d8]), src + CDIM);
            cp16(smem_u32(&vs [row * QKS + d8]), src + 2 * CDIM);
        } else {
            #pragma unroll
            for (int j = 0; j < 8; j++) {
                qs [row * QKS + d8 + j] = __float2half_rn(bq[d8 + j]);
                kss[row * QKS + d8 + j] = __float2half_rn(bq[CDIM + d8 + j]);
                vs [row * QKS + d8 + j] = __float2half_rn(bq[2 * CDIM + d8 + j]);
            }
        }
    }
    // zero V pad rows 196..207
    for (int idx = tid; idx < 12 * QKS; idx += 256)
        vs[(HW + idx / QKS) * QKS + (idx % QKS)] = __float2half_rn(0.f);
    asm volatile("cp.async.commit_group;\n");
    asm volatile("cp.async.wait_group 0;\n");
    __syncthreads();

    // ---- bias tables via MMA: bhf[196][27] = Q*RhT, bwf = Q*RwT ----
    for (int st = warp; st < 13; st += 8) {
        float ba[4][4], bb2[4][4];
        #pragma unroll
        for (int g = 0; g < 4; g++)
            #pragma unroll
            for (int r = 0; r < 4; r++) { ba[g][r] = 0.f; bb2[g][r] = 0.f; }
        int mrow = st * 16;
        #pragma unroll
        for (int kk = 0; kk < HD; kk += 16) {
            uint32_t qf[4];
            int ar = mrow + fr; if (ar > HW - 1) ar = HW - 1;
            ldsm4(qf[0], qf[1], qf[2], qf[3], qs_b + (ar * QKS + kk + fc) * 2);
            #pragma unroll
            for (int g = 0; g < 2; g++) {
                uint32_t hf0[2], hf1[2], wf0[2], wf1[2];
                ldsm4(hf0[0], hf1[0], hf0[1], hf1[1],
                      rh_b + ((g * 16 + fr) * QKS + kk + fc) * 2);
                ldsm4(wf0[0], wf1[0], wf0[1], wf1[1],
                      rw_b + ((g * 16 + fr) * QKS + kk + fc) * 2);
                mma16816(ba[2 * g],      qf, hf0);
                mma16816(ba[2 * g + 1],  qf, hf1);
                mma16816(bb2[2 * g],     qf, wf0);
                mma16816(bb2[2 * g + 1], qf, wf1);
            }
        }
        #pragma unroll
        for (int g = 0; g < 4; g++) {
            int col = g * 8 + tr * 2;
            int r0 = mrow + gq;
            if (r0 < HW) {
                *(float2*)&bhf[r0 * BFS + col] = make_float2(ba[g][0], ba[g][1]);
                *(float2*)&bwf[r0 * BFS + col] = make_float2(bb2[g][0], bb2[g][1]);
            }
            if (r0 + 8 < HW) {
                *(float2*)&bhf[(r0 + 8) * BFS + col] = make_float2(ba[g][2], ba[g][3]);
                *(float2*)&bwf[(r0 + 8) * BFS + col] = make_float2(bb2[g][2], bb2[g][3]);
            }
        }
    }
    __syncthreads();

    int stripe = warp >> 1, nh = warp & 1;
    int ngr   = nh ? 6 : 7;
    int nbase = nh ? 112 : 0;
    int barid = 1 + stripe;

    for (int c = 0; c < 4; c++) {
        int q0 = c * 64;
        int rows = (HW - q0 < 64) ? (HW - q0) : 64;
        int nstripes = (rows + 15) >> 4;

        if (stripe < nstripes) {
            int mrow = q0 + stripe * 16;
            float sacc[7][2][4];
            #pragma unroll
            for (int g = 0; g < 7; g++)
                #pragma unroll
                for (int u = 0; u < 2; u++)
                    #pragma unroll
                    for (int r = 0; r < 4; r++) sacc[g][u][r] = 0.f;

            // ---- QK^T MMA ----
            #pragma unroll
            for (int kk = 0; kk < HD; kk += 16) {
                uint32_t af[4];
                int ar = mrow + fr; if (ar > HW - 1) ar = HW - 1;
                ldsm4(af[0], af[1], af[2], af[3],
                      qs_b + (ar * QKS + kk + fc) * 2);
                #pragma unroll
                for (int g = 0; g < 7; g++) {
                    if (g < ngr) {
                        int br = nbase + g * 16 + fr; if (br > HW - 1) br = HW - 1;
                        uint32_t bf0[2], bf1[2];
                        ldsm4(bf0[0], bf1[0], bf0[1], bf1[1],
                              ks_b + (br * QKS + kk + fc) * 2);
                        mma16816(sacc[g][0], af, bf0);
                        mma16816(sacc[g][1], af, bf1);
                    }
                }
            }

            // ---- register softmax ----
            int qa = mrow + gq, qb = qa + 8;
            int qca = qa < HW ? qa : HW - 1;
            int qcb = qb < HW ? qb : HW - 1;
            int hqa = qca / WIN, wqa = qca % WIN;
            int hqb = qcb / WIN, wqb = qcb % WIN;
            const float* bha = &bhf[qca * BFS + (WIN - 1)];
            const float* bwa = &bwf[qca * BFS + (WIN - 1)];
            const float* bhb = &bhf[qcb * BFS + (WIN - 1)];
            const float* bwb = &bwf[qcb * BFS + (WIN - 1)];

            float mx0 = -1e30f, mx1 = -1e30f;
            #pragma unroll
            for (int g = 0; g < 7; g++) {
                if (g < ngr) {
                    #pragma unroll
                    for (int u = 0; u < 2; u++) {
                        int col0 = nbase + g * 16 + u * 8 + tr * 2;
                        #pragma unroll
                        for (int cc = 0; cc < 2; cc++) {
                            int col = col0 + cc;
                            int kh = col / WIN, kw = col % WIN;
                            bool valid = col < HW;
                            float t0 = valid
                                ? sacc[g][u][cc] * 0.125f + bha[hqa - kh] + bwa[wqa - kw]
                                : -1e30f;
                            float t1 = valid
                                ? sacc[g][u][2 + cc] * 0.125f + bhb[hqb - kh] + bwb[wqb - kw]
                                : -1e30f;
                            sacc[g][u][cc]     = t0;
                            sacc[g][u][2 + cc] = t1;
                            mx0 = fmaxf(mx0, t0);
                            mx1 = fmaxf(mx1, t1);
                        }
                    }
                }
            }
            mx0 = fmaxf(mx0, __shfl_xor_sync(~0u, mx0, 1));
            mx0 = fmaxf(mx0, __shfl_xor_sync(~0u, mx0, 2));
            mx1 = fmaxf(mx1, __shfl_xor_sync(~0u, mx1, 1));
            mx1 = fmaxf(mx1, __shfl_xor_sync(~0u, mx1, 2));
            if (tr == 0) {
                redA[(stripe * 16 + gq) * 2 + nh]     = mx0;
                redA[(stripe * 16 + gq + 8) * 2 + nh] = mx1;
            }
            barpair(barid);
            mx0 = fmaxf(mx0, redA[(stripe * 16 + gq) * 2 + (nh ^ 1)]);
            mx1 = fmaxf(mx1, redA[(stripe * 16 + gq + 8) * 2 + (nh ^ 1)]);

            float s0 = 0.f, s1 = 0.f;
            #pragma unroll
            for (int g = 0; g < 7; g++) {
                if (g < ngr) {
                    #pragma unroll
                    for (int u = 0; u < 2; u++) {
                        #pragma unroll
                        for (int cc = 0; cc < 2; cc++) {
                            float e0 = __expf(sacc[g][u][cc]     - mx0);
                            float e1 = __expf(sacc[g][u][2 + cc] - mx1);
                            sacc[g][u][cc]     = e0;
                            sacc[g][u][2 + cc] = e1;
                            s0 += e0; s1 += e1;
                        }
                    }
                }
            }
            s0 += __shfl_xor_sync(~0u, s0, 1);
            s0 += __shfl_xor_sync(~0u, s0, 2);
            s1 += __shfl_xor_sync(~0u, s1, 1);
            s1 += __shfl_xor_sync(~0u, s1, 2);
            if (tr == 0) {
                redB[(stripe * 16 + gq) * 2 + nh]     = s0;
                redB[(stripe * 16 + gq + 8) * 2 + nh] = s1;
            }
            barpair(barid);
            s0 += redB[(stripe * 16 + gq) * 2 + (nh ^ 1)];
            s1 += redB[(stripe * 16 + gq + 8) * 2 + (nh ^ 1)];
            float inv0 = 1.f / s0, inv1 = 1.f / s1;

            int lr0 = stripe * 16 + gq;
            #pragma unroll
            for (int g = 0; g < 7; g++) {
                if (g < ngr) {
                    #pragma unroll
                    for (int u = 0; u < 2; u++) {
                        int col0 = nbase + g * 16 + u * 8 + tr * 2;
                        *(__half2*)&ps[lr0 * VPS + col0] =
                            __floats2half2_rn(sacc[g][u][0] * inv0,
                                              sacc[g][u][1] * inv0);
                        *(__half2*)&ps[(lr0 + 8) * VPS + col0] =
                            __floats2half2_rn(sacc[g][u][2] * inv1,
                                              sacc[g][u][3] * inv1);
                    }
                }
            }
            barpair(barid);   // partner's P rows complete before PV reads

            // ---- PV: B-fragments from row-major V via ldmatrix.trans ----
            int d0b = nh * 32;
            float oacc[4][4];
            #pragma unroll
            for (int ni = 0; ni < 4; ni++)
                #pragma unroll
                for (int r = 0; r < 4; r++) oacc[ni][r] = 0.f;

            #pragma unroll
            for (int kk = 0; kk < 208; kk += 16) {
                uint32_t af[4];
                ldsm4(af[0], af[1], af[2], af[3],
                      ps_b + ((stripe * 16 + fr) * VPS + kk + fc) * 2);
                #pragma unroll
                for (int g = 0; g < 2; g++) {
                    uint32_t bf0[2], bf1[2];
                    ldsm4t(bf0[0], bf0[1], bf1[0], bf1[1],
                           vs_b + ((kk + fr) * QKS + d0b + g * 16 + fc) * 2);
                    mma16816(oacc[2 * g],     af, bf0);
                    mma16816(oacc[2 * g + 1], af, bf1);
                }
            }
            #pragma unroll
            for (int ni = 0; ni < 4; ni++) {
                int col = head * HD + d0b + ni * 8 + tr * 2;
                #pragma unroll
                for (int h = 0; h < 2; h++) {
                    int grow = q0 + stripe * 16 + gq + 8 * h;
                    if (grow < HW) {
                        int gi = gtab[grow];
                        if (gi >= 0) {
                            __half* op = g_attn + (size_t)gi * CDIM + col;
                            *(__half2*)op = __floats2half2_rn(oacc[ni][2 * h],
                                                              oacc[ni][2 * h + 1]);
                        }
                    }
                }
            }
        }
    }
}

// ---------------- launcher ----------------
extern "C" void kernel_launch(void* const* d_in, const int* in_sizes, int n_in,
                              void* d_out, int out_size)
{
    const float* x      = (const float*)d_in[0];
    const float* g1     = (const float*)d_in[1];
    const float* b1     = (const float*)d_in[2];
    const float* w_qkv  = (const float*)d_in[3];
    const float* b_qkv  = (const float*)d_in[4];
    const float* w_proj = (const float*)d_in[5];
    const float* b_proj = (const float*)d_in[6];
    const float* rel_h  = (const float*)d_in[7];
    const float* rel_w  = (const float*)d_in[8];
    const float* g2     = (const float*)d_in[9];
    const float* b2     = (const float*)d_in[10];
    const float* w1     = (const float*)d_in[11];
    const float* b1m    = (const float*)d_in[12];
    const float* w2     = (const float*)d_in[13];
    const float* b2m    = (const float*)d_in[14];
    float* out = (float*)d_out;

    __half *p_xn1, *p_qkv, *p_attn, *p_xn2, *p_hid;
    __half *p_wqkvT, *p_wprojT, *p_w1T, *p_w2T;
    float *p_x2;
    cudaGetSymbolAddress((void**)&p_xn1,   g_xn1);
    cudaGetSymbolAddress((void**)&p_qkv,   g_qkv);
    cudaGetSymbolAddress((void**)&p_attn,  g_attn);
    cudaGetSymbolAddress((void**)&p_x2,    g_x2);
    cudaGetSymbolAddress((void**)&p_xn2,   g_xn2);
    cudaGetSymbolAddress((void**)&p_hid,   g_hid);
    cudaGetSymbolAddress((void**)&p_wqkvT, g_wqkvT);
    cudaGetSymbolAddress((void**)&p_wprojT,g_wprojT);
    cudaGetSymbolAddress((void**)&p_w1T,   g_w1T);
    cudaGetSymbolAddress((void**)&p_w2T,   g_w2T);

    static int attr_set = 0;
    if (!attr_set) {
        cudaFuncSetAttribute(attn_kernel,
            cudaFuncAttributeMaxDynamicSharedMemorySize, ATTN_SMEM_BYTES);
        cudaFuncSetAttribute(hgemm_kernel,
            cudaFuncAttributeMaxDynamicSharedMemorySize, GSMEM);
        attr_set = 1;
    }

    // 0) all weight transposes in one launch
    f2hT_all_kernel<<<6912, dim3(32, 8)>>>(w_qkv, w_proj, w1, w2);

    // 1) LN1 -> g_xn1 (half)
    ln_kernel<<<TOKG / 8, 256>>>(x, p_xn1, g1, b1);

    // 2) QKV GEMM -> g_qkv (half)
    {
        dim3 grid((3 * CDIM) / 128, TOKG / 128);
        hgemm_kernel<<<grid, 256, GSMEM>>>(p_xn1, p_wqkvT, b_qkv, nullptr,
                                           nullptr, p_qkv,
                                           TOKG, 3 * CDIM, CDIM, 0);
    }

    // 3) tensor-core attention -> g_attn (half)
    attn_kernel<<<dim3(NW, NHEAD), 256, ATTN_SMEM_BYTES>>>(rel_h, rel_w, b_qkv);

    // 4) proj GEMM + residual(x) -> g_x2 (float)
    {
        dim3 grid(CDIM / 128, TOKG / 128);
        hgemm_kernel<<<grid, 256, GSMEM>>>(p_attn, p_wprojT, b_proj, x,
                                           p_x2, nullptr,
                                           TOKG, CDIM, CDIM, 2);
    }

    // 5) LN2 -> g_xn2 (half)
    ln_kernel<<<TOKG / 8, 256>>>(p_x2, p_xn2, g2, b2);

    // 6) FC1 + GELU -> g_hid (half)
    {
        dim3 grid(MLPD / 128, TOKG / 128);
        hgemm_kernel<<<grid, 256, GSMEM>>>(p_xn2, p_w1T, b1m, nullptr,
                                           nullptr, p_hid,
                                           TOKG, MLPD, CDIM, 1);
    }

    // 7) FC2 + residual(g_x2) -> out (float)
    {
        dim3 grid(CDIM / 128, TOKG / 128);
        hgemm_kernel<<<grid, 256, GSMEM>>>(p_hid, p_w2T, b2m, p_x2,
                                           out, nullptr,
                                           TOKG, CDIM, MLPD, 2);
    }
}